// round 4
// baseline (speedup 1.0000x reference)
#include <cuda_runtime.h>
#include <cuda_bf16.h>
#include <cstdint>

#define NPROT 100000
#define NSUB  50000
#define HDIM  64
#define PDIM  1024
#define SDIM  512
#define EPROT 3200000
#define ESUB  1600000
#define ELNK  2000000

// ---------------- scratch (static device allocation; no cudaMalloc) --------
#define OFF_P0 0L
#define OFF_P1 (OFF_P0 + (long)NPROT*64)
#define OFF_P2 (OFF_P1 + (long)NPROT*64)
#define OFF_S0 (OFF_P2 + (long)NPROT*64)
#define OFF_S1 (OFF_S0 + (long)NSUB*64)
#define OFF_S2 (OFF_S1 + (long)NSUB*64)
#define OFF_DP (OFF_S2 + (long)NSUB*64)
#define OFF_DS (OFF_DP + NPROT)
#define OFF_MP (OFF_DS + NSUB)
#define OFF_MS (OFF_MP + 64*64)
#define OFF_C  (OFF_MS + 64*64)
#define SCRATCH_TOTAL (OFF_C + 64)

__device__ __align__(256) float g_scratch[SCRATCH_TOTAL];

// ---------------- small elementwise kernels --------------------------------
__global__ void k_fill1(float* p, int n) {
    int i = blockIdx.x * blockDim.x + threadIdx.x;
    if (i < n) p[i] = 1.0f;
}

__global__ void k_count_deg(const int* __restrict__ dst, int E, float* __restrict__ deg) {
    int i = blockIdx.x * blockDim.x + threadIdx.x;
    if (i < E) atomicAdd(&deg[dst[i]], 1.0f);
}

// rsqrt on contiguous dinv region [NPROT+NSUB], plus fold Wproj@Wl1 -> Mp/Ms/c
__global__ void k_rsqrt_prep(float* __restrict__ dinv,
                             const float* __restrict__ Wproj, const float* __restrict__ bproj,
                             const float* __restrict__ Wl1, const float* __restrict__ bl1,
                             float* __restrict__ Mp, float* __restrict__ Ms, float* __restrict__ c) {
    int gid = blockIdx.x * blockDim.x + threadIdx.x;
    if (gid < NPROT + NSUB) dinv[gid] = rsqrtf(dinv[gid]);
    if (gid < 128 * 64) {
        int a = gid >> 6, j = gid & 63;
        float s = 0.f;
        #pragma unroll 4
        for (int t = 0; t < 128; t++) s = fmaf(Wproj[a * 128 + t], Wl1[t * 64 + j], s);
        if (a < 64) Mp[a * 64 + j] = s;
        else        Ms[(a - 64) * 64 + j] = s;
    }
    if (gid < 64) {
        float s = bl1[gid];
        #pragma unroll 4
        for (int t = 0; t < 128; t++) s = fmaf(bproj[t], Wl1[t * 64 + gid], s);
        c[gid] = s;
    }
}

// out[row,:] = dinv[row] * acc[row,:] + bias[:]
__global__ void k_finish(const float* __restrict__ acc, const float* __restrict__ dinv,
                         const float* __restrict__ bias, float* __restrict__ out, int N) {
    int i = blockIdx.x * blockDim.x + threadIdx.x;
    if (i >= N * 16) return;
    int row = i >> 4;
    int c4 = (i & 15) << 2;
    float d = dinv[row];
    float4 a = *(const float4*)&acc[(long)row * 64 + c4];
    float4 b = *(const float4*)&bias[c4];
    float4 o = make_float4(fmaf(a.x, d, b.x), fmaf(a.y, d, b.y),
                           fmaf(a.z, d, b.z), fmaf(a.w, d, b.w));
    *(float4*)&out[(long)row * 64 + c4] = o;
}

// ---------------- GEMM: out[M,64] = (X[M,K] @ W[K,64]) * dinv[row] ---------
// 128x64 block tile, packed f32x2 FMA (FFMA2). 256 threads:
//   tx = tid&15 -> 4 output cols (2 packed pairs), ty = tid>>4 -> rows ty+16i, i<8
__device__ __forceinline__ unsigned long long dupf(float x) {
    unsigned int u = __float_as_uint(x);
    return (unsigned long long)u | ((unsigned long long)u << 32);
}

template <int K>
__global__ void __launch_bounds__(256) k_gemm_n64(
        const float* __restrict__ X, const float* __restrict__ W,
        const float* __restrict__ dinv,
        float* __restrict__ outH, float* __restrict__ outAcc, int M) {
    __shared__ __align__(16) unsigned long long Xsd[128 * 16]; // {x,x} packed
    __shared__ __align__(16) float Ws[16 * 64];
    const int tid = threadIdx.x;
    const int tx = tid & 15;
    const int ty = tid >> 4;
    const int row0 = blockIdx.x * 128;

    unsigned long long acc[8][2];
    #pragma unroll
    for (int i = 0; i < 8; i++) { acc[i][0] = 0ull; acc[i][1] = 0ull; }

    const int xrow = tid >> 1;              // 0..127
    const int xcg = (tid & 1) * 8;          // 0 or 8 (8 floats each)
    const int wr = tid >> 4;                // 0..15
    const int wc = (tid & 15) << 2;

    for (int kk = 0; kk < K; kk += 16) {
        float4 a0 = make_float4(0.f, 0.f, 0.f, 0.f), a1 = a0;
        if (row0 + xrow < M) {
            const float* xp = &X[(long)(row0 + xrow) * K + kk + xcg];
            a0 = *(const float4*)xp;
            a1 = *(const float4*)(xp + 4);
        }
        unsigned long long* xd = &Xsd[xrow * 16 + xcg];
        xd[0] = dupf(a0.x); xd[1] = dupf(a0.y); xd[2] = dupf(a0.z); xd[3] = dupf(a0.w);
        xd[4] = dupf(a1.x); xd[5] = dupf(a1.y); xd[6] = dupf(a1.z); xd[7] = dupf(a1.w);
        *(float4*)&Ws[wr * 64 + wc] = *(const float4*)&W[(long)(kk + wr) * 64 + wc];
        __syncthreads();

        #pragma unroll
        for (int k = 0; k < 16; k++) {
            ulonglong2 w2 = *(const ulonglong2*)&Ws[k * 64 + (tx << 2)];
            #pragma unroll
            for (int i = 0; i < 8; i++) {
                unsigned long long xx = Xsd[(ty + (i << 4)) * 16 + k];
                asm("fma.rn.f32x2 %0, %1, %2, %0;" : "+l"(acc[i][0]) : "l"(xx), "l"(w2.x));
                asm("fma.rn.f32x2 %0, %1, %2, %0;" : "+l"(acc[i][1]) : "l"(xx), "l"(w2.y));
            }
        }
        __syncthreads();
    }

    #pragma unroll
    for (int i = 0; i < 8; i++) {
        int r = row0 + ty + (i << 4);
        if (r < M) {
            float d = dinv ? dinv[r] : 1.0f;
            unsigned int l0, h0, l1, h1;
            asm("mov.b64 {%0,%1}, %2;" : "=r"(l0), "=r"(h0) : "l"(acc[i][0]));
            asm("mov.b64 {%0,%1}, %2;" : "=r"(l1), "=r"(h1) : "l"(acc[i][1]));
            float4 v = make_float4(__uint_as_float(l0) * d, __uint_as_float(h0) * d,
                                   __uint_as_float(l1) * d, __uint_as_float(h1) * d);
            *(float4*)&outH[(long)r * 64 + (tx << 2)] = v;
            if (outAcc) *(float4*)&outAcc[(long)r * 64 + (tx << 2)] = v;
        }
    }
}

// ---------------- edge scatter: acc[dst,:] += hs[src,:] --------------------
__global__ void k_scatter(const int* __restrict__ src, const int* __restrict__ dst,
                          int E, const float* __restrict__ hs, float* __restrict__ acc) {
    int gid = blockIdx.x * blockDim.x + threadIdx.x;
    int e = gid >> 4;
    if (e >= E) return;
    int j = (gid & 15) << 2;
    int s = src[e];
    int d = dst[e];
    float4 v = *(const float4*)&hs[(long)s * 64 + j];
    float* addr = &acc[(long)d * 64 + j];
    asm volatile("red.global.add.v4.f32 [%0], {%1, %2, %3, %4};"
                 :: "l"(addr), "f"(v.x), "f"(v.y), "f"(v.z), "f"(v.w)
                 : "memory");
}

// ---------------- link predictor: out[e] = relu(A[ep]+B[es]+c)@Wl2 + bl2 ---
__global__ void k_link(const int* __restrict__ ep, const int* __restrict__ es,
                       const float* __restrict__ A, const float* __restrict__ B,
                       const float* __restrict__ cvec, const float* __restrict__ wl2,
                       const float* __restrict__ bl2, float* __restrict__ out) {
    int lane = threadIdx.x & 31;
    int half = lane >> 4;
    int sub = lane & 15;
    int warp = (blockIdx.x * blockDim.x + threadIdx.x) >> 5;
    if (warp * 2 >= ELNK) return;
    int e = warp * 2 + half;

    float4 c4 = *(const float4*)&cvec[sub << 2];
    float4 w4 = *(const float4*)&wl2[sub << 2];

    long pi = (long)ep[e];
    long si = (long)es[e];
    float4 a = *(const float4*)&A[pi * 64 + (sub << 2)];
    float4 b = *(const float4*)&B[si * 64 + (sub << 2)];

    float r = fmaxf(a.x + b.x + c4.x, 0.f) * w4.x
            + fmaxf(a.y + b.y + c4.y, 0.f) * w4.y
            + fmaxf(a.z + b.z + c4.z, 0.f) * w4.z
            + fmaxf(a.w + b.w + c4.w, 0.f) * w4.w;

    #pragma unroll
    for (int off = 8; off > 0; off >>= 1)
        r += __shfl_down_sync(0xffffffffu, r, off, 16);

    if (sub == 0) out[e] = r + bl2[0];
}

// ---------------- launch ----------------------------------------------------
extern "C" void kernel_launch(void* const* d_in, const int* in_sizes, int n_in,
                              void* d_out, int out_size) {
    const float* x_p  = (const float*)d_in[0];
    const float* x_s  = (const float*)d_in[1];
    const int*   ei_p = (const int*)d_in[2];   // [2, EPROT] int32
    const int*   ei_s = (const int*)d_in[3];   // [2, ESUB]  int32
    const int*   ep   = (const int*)d_in[4];
    const int*   es   = (const int*)d_in[5];
    const float *Wp1 = (const float*)d_in[6],  *bp1 = (const float*)d_in[7];
    const float *Ws1 = (const float*)d_in[8],  *bs1 = (const float*)d_in[9];
    const float *Wp2 = (const float*)d_in[10], *bp2 = (const float*)d_in[11];
    const float *Ws2 = (const float*)d_in[12], *bs2 = (const float*)d_in[13];
    const float *Wproj = (const float*)d_in[14], *bproj = (const float*)d_in[15];
    const float *Wl1 = (const float*)d_in[16], *bl1 = (const float*)d_in[17];
    const float *Wl2 = (const float*)d_in[18], *bl2 = (const float*)d_in[19];
    float* out = (float*)d_out;

    float* scratch = nullptr;
    cudaGetSymbolAddress((void**)&scratch, g_scratch);
    float* P0 = scratch + OFF_P0;
    float* P1 = scratch + OFF_P1;
    float* P2 = scratch + OFF_P2;
    float* S0 = scratch + OFF_S0;
    float* S1 = scratch + OFF_S1;
    float* S2 = scratch + OFF_S2;
    float* dinvP = scratch + OFF_DP;   // dinvP/dinvS contiguous [NPROT+NSUB]
    float* dinvS = scratch + OFF_DS;
    float* Mp = scratch + OFF_MP;
    float* Ms = scratch + OFF_MS;
    float* cv = scratch + OFF_C;

    const int T = 256;
    const int gP = (NPROT + 127) / 128;
    const int gS = (NSUB + 127) / 128;
    const int scatP = (int)(((long)EPROT * 16 + T - 1) / T);
    const int scatS = (int)(((long)ESUB * 16 + T - 1) / T);
    const int finP = (NPROT * 16 + T - 1) / T;
    const int finS = (NSUB * 16 + T - 1) / T;

    // launch order chosen so ncu (-s 5 -c 1) profiles the protein scatter (#5)
    k_fill1<<<(NPROT + NSUB + T - 1) / T, T>>>(dinvP, NPROT + NSUB);              // 0
    k_count_deg<<<(EPROT + T - 1) / T, T>>>(ei_p + EPROT, EPROT, dinvP);          // 1
    k_count_deg<<<(ESUB + T - 1) / T, T>>>(ei_s + ESUB, ESUB, dinvS);             // 2
    k_rsqrt_prep<<<(NPROT + NSUB + T - 1) / T, T>>>(dinvP, Wproj, bproj, Wl1, bl1,
                                                    Mp, Ms, cv);                  // 3
    // ---- protein conv1 ----
    k_gemm_n64<PDIM><<<gP, T>>>(x_p, Wp1, dinvP, P1, P2, NPROT);                  // 4
    k_scatter<<<scatP, T>>>(ei_p, ei_p + EPROT, EPROT, P1, P2);                   // 5 (profiled)
    k_finish<<<finP, T>>>(P2, dinvP, bp1, P0, NPROT);
    // ---- protein conv2 ----
    k_gemm_n64<HDIM><<<gP, T>>>(P0, Wp2, dinvP, P1, P2, NPROT);
    k_scatter<<<scatP, T>>>(ei_p, ei_p + EPROT, EPROT, P1, P2);
    k_finish<<<finP, T>>>(P2, dinvP, bp2, P0, NPROT);
    // ---- protein A-table: A = z_p @ Mp ----
    k_gemm_n64<HDIM><<<gP, T>>>(P0, Mp, nullptr, P1, nullptr, NPROT);

    // ---- substrate conv1 ----
    k_gemm_n64<SDIM><<<gS, T>>>(x_s, Ws1, dinvS, S1, S2, NSUB);
    k_scatter<<<scatS, T>>>(ei_s, ei_s + ESUB, ESUB, S1, S2);
    k_finish<<<finS, T>>>(S2, dinvS, bs1, S0, NSUB);
    // ---- substrate conv2 ----
    k_gemm_n64<HDIM><<<gS, T>>>(S0, Ws2, dinvS, S1, S2, NSUB);
    k_scatter<<<scatS, T>>>(ei_s, ei_s + ESUB, ESUB, S1, S2);
    k_finish<<<finS, T>>>(S2, dinvS, bs2, S0, NSUB);
    // ---- substrate B-table: B = z_s @ Ms ----
    k_gemm_n64<HDIM><<<gS, T>>>(S0, Ms, nullptr, S1, nullptr, NSUB);

    // ---- link prediction ----
    int linkBlocks = (int)(((long)(ELNK / 2) * 32 + T - 1) / T);
    k_link<<<linkBlocks, T>>>(ep, es, P1, S1, cv, Wl2, bl2, out);
}

// round 6
// speedup vs baseline: 1.1565x; 1.1565x over previous
#include <cuda_runtime.h>
#include <cuda_bf16.h>
#include <cstdint>

#define NPROT 100000
#define NSUB  50000
#define HDIM  64
#define PDIM  1024
#define SDIM  512
#define EPROT 3200000
#define ESUB  1600000
#define ELNK  2000000

// ---------------- scratch (static device allocation; no cudaMalloc) --------
#define OFF_P0 0L
#define OFF_P1 (OFF_P0 + (long)NPROT*64)
#define OFF_P2 (OFF_P1 + (long)NPROT*64)
#define OFF_S0 (OFF_P2 + (long)NPROT*64)
#define OFF_S1 (OFF_S0 + (long)NSUB*64)
#define OFF_S2 (OFF_S1 + (long)NSUB*64)
#define OFF_DP (OFF_S2 + (long)NSUB*64)
#define OFF_DS (OFF_DP + NPROT)
#define OFF_MP (OFF_DS + NSUB)
#define OFF_MS (OFF_MP + 64*64)
#define OFF_C  (OFF_MS + 64*64)
#define SCRATCH_TOTAL (OFF_C + 64)

__device__ __align__(256) float g_scratch[SCRATCH_TOTAL];

// ---------------- small kernels --------------------------------------------
__global__ void k_fill1(float* p, int n) {
    int i = blockIdx.x * blockDim.x + threadIdx.x;
    if (i < n) p[i] = 1.0f;
}

// both graphs' degree counts in one kernel
__global__ void k_count_both(const int* __restrict__ dstP, const int* __restrict__ dstS,
                             float* __restrict__ degP, float* __restrict__ degS) {
    int i = blockIdx.x * blockDim.x + threadIdx.x;
    if (i < EPROT) atomicAdd(&degP[dstP[i]], 1.0f);
    else if (i < EPROT + ESUB) atomicAdd(&degS[dstS[i - EPROT]], 1.0f);
}

// rsqrt on contiguous dinv region [NPROT+NSUB], plus fold Wproj@Wl1 -> Mp/Ms/c
__global__ void k_rsqrt_prep(float* __restrict__ dinv,
                             const float* __restrict__ Wproj, const float* __restrict__ bproj,
                             const float* __restrict__ Wl1, const float* __restrict__ bl1,
                             float* __restrict__ Mp, float* __restrict__ Ms, float* __restrict__ c) {
    int gid = blockIdx.x * blockDim.x + threadIdx.x;
    if (gid < NPROT + NSUB) dinv[gid] = rsqrtf(dinv[gid]);
    if (gid < 128 * 64) {
        int a = gid >> 6, j = gid & 63;
        float s = 0.f;
        #pragma unroll 4
        for (int t = 0; t < 128; t++) s = fmaf(Wproj[a * 128 + t], Wl1[t * 64 + j], s);
        if (a < 64) Mp[a * 64 + j] = s;
        else        Ms[(a - 64) * 64 + j] = s;
    }
    if (gid < 64) {
        float s = bl1[gid];
        #pragma unroll 4
        for (int t = 0; t < 128; t++) s = fmaf(bproj[t], Wl1[t * 64 + gid], s);
        c[gid] = s;
    }
}

// ---------------- GEMM: out[M,64] = (f(X)[M,K] @ W[K,64]) * dinvOut[row] ----
// f(X) = dinvIn[row]*X + biasIn[col] when FOLD (fuses the previous conv's
// epilogue into this GEMM's X load), else identity.
// 64x64 block tile, 256 threads, 4x4 per thread. Known-good round-2 shape.
template <int K, bool FOLD>
__global__ void __launch_bounds__(256) k_gemm_n64(
        const float* __restrict__ X, const float* __restrict__ W,
        const float* __restrict__ dinvOut,
        const float* __restrict__ dinvIn, const float* __restrict__ biasIn,
        float* __restrict__ outH, float* __restrict__ outAcc, int M) {
    __shared__ float Xs[64][16];
    __shared__ float Ws[16][64];
    const int tid = threadIdx.x;
    const int tx = tid & 15;
    const int ty = tid >> 4;
    const int row0 = blockIdx.x * 64;

    float acc[4][4];
    #pragma unroll
    for (int i = 0; i < 4; i++)
        #pragma unroll
        for (int j = 0; j < 4; j++) acc[i][j] = 0.f;

    const int lr = tid >> 2;               // X load row 0..63
    const int lc = (tid & 3) << 2;         // X load col4
    const int wr = tid >> 4;               // W load row 0..15
    const int wc = (tid & 15) << 2;        // W load col4

    for (int kk = 0; kk < K; kk += 16) {
        float4 xv = make_float4(0.f, 0.f, 0.f, 0.f);
        if (row0 + lr < M) {
            xv = *(const float4*)&X[(long)(row0 + lr) * K + kk + lc];
            if (FOLD) {
                float di = dinvIn[row0 + lr];
                float4 bb = *(const float4*)&biasIn[kk + lc];
                xv = make_float4(fmaf(xv.x, di, bb.x), fmaf(xv.y, di, bb.y),
                                 fmaf(xv.z, di, bb.z), fmaf(xv.w, di, bb.w));
            }
        }
        *(float4*)&Xs[lr][lc] = xv;
        *(float4*)&Ws[wr][wc] = *(const float4*)&W[(long)(kk + wr) * 64 + wc];
        __syncthreads();
        #pragma unroll
        for (int k = 0; k < 16; k++) {
            float4 wv = *(const float4*)&Ws[k][tx << 2];
            float xr[4];
            #pragma unroll
            for (int i = 0; i < 4; i++) xr[i] = Xs[ty + (i << 4)][k];
            #pragma unroll
            for (int i = 0; i < 4; i++) {
                acc[i][0] = fmaf(xr[i], wv.x, acc[i][0]);
                acc[i][1] = fmaf(xr[i], wv.y, acc[i][1]);
                acc[i][2] = fmaf(xr[i], wv.z, acc[i][2]);
                acc[i][3] = fmaf(xr[i], wv.w, acc[i][3]);
            }
        }
        __syncthreads();
    }

    #pragma unroll
    for (int i = 0; i < 4; i++) {
        int r = row0 + ty + (i << 4);
        if (r < M) {
            float d = dinvOut ? dinvOut[r] : 1.0f;
            float4 v = make_float4(acc[i][0] * d, acc[i][1] * d, acc[i][2] * d, acc[i][3] * d);
            *(float4*)&outH[(long)r * 64 + (tx << 2)] = v;
            if (outAcc) *(float4*)&outAcc[(long)r * 64 + (tx << 2)] = v;
        }
    }
}

// ---------------- edge scatter: acc[dst,:] += hs[src,:] --------------------
__global__ void k_scatter(const int* __restrict__ src, const int* __restrict__ dst,
                          int E, const float* __restrict__ hs, float* __restrict__ acc) {
    int gid = blockIdx.x * blockDim.x + threadIdx.x;
    int e = gid >> 4;
    if (e >= E) return;
    int j = (gid & 15) << 2;
    int s = src[e];
    int d = dst[e];
    float4 v = *(const float4*)&hs[(long)s * 64 + j];
    float* addr = &acc[(long)d * 64 + j];
    asm volatile("red.global.add.v4.f32 [%0], {%1, %2, %3, %4};"
                 :: "l"(addr), "f"(v.x), "f"(v.y), "f"(v.z), "f"(v.w)
                 : "memory");
}

// ---------------- link predictor: out[e] = relu(A[ep]+B[es]+c)@Wl2 + bl2 ---
__global__ void k_link(const int* __restrict__ ep, const int* __restrict__ es,
                       const float* __restrict__ A, const float* __restrict__ B,
                       const float* __restrict__ cvec, const float* __restrict__ wl2,
                       const float* __restrict__ bl2, float* __restrict__ out) {
    int lane = threadIdx.x & 31;
    int half = lane >> 4;
    int sub = lane & 15;
    int warp = (blockIdx.x * blockDim.x + threadIdx.x) >> 5;
    if (warp * 2 >= ELNK) return;
    int e = warp * 2 + half;

    float4 c4 = *(const float4*)&cvec[sub << 2];
    float4 w4 = *(const float4*)&wl2[sub << 2];

    long pi = (long)ep[e];
    long si = (long)es[e];
    float4 a = *(const float4*)&A[pi * 64 + (sub << 2)];
    float4 b = *(const float4*)&B[si * 64 + (sub << 2)];

    float r = fmaxf(a.x + b.x + c4.x, 0.f) * w4.x
            + fmaxf(a.y + b.y + c4.y, 0.f) * w4.y
            + fmaxf(a.z + b.z + c4.z, 0.f) * w4.z
            + fmaxf(a.w + b.w + c4.w, 0.f) * w4.w;

    #pragma unroll
    for (int off = 8; off > 0; off >>= 1)
        r += __shfl_down_sync(0xffffffffu, r, off, 16);

    if (sub == 0) out[e] = r + bl2[0];
}

// ---------------- launch ----------------------------------------------------
extern "C" void kernel_launch(void* const* d_in, const int* in_sizes, int n_in,
                              void* d_out, int out_size) {
    const float* x_p  = (const float*)d_in[0];
    const float* x_s  = (const float*)d_in[1];
    const int*   ei_p = (const int*)d_in[2];   // [2, EPROT] int32
    const int*   ei_s = (const int*)d_in[3];   // [2, ESUB]  int32
    const int*   ep   = (const int*)d_in[4];
    const int*   es   = (const int*)d_in[5];
    const float *Wp1 = (const float*)d_in[6],  *bp1 = (const float*)d_in[7];
    const float *Ws1 = (const float*)d_in[8],  *bs1 = (const float*)d_in[9];
    const float *Wp2 = (const float*)d_in[10], *bp2 = (const float*)d_in[11];
    const float *Ws2 = (const float*)d_in[12], *bs2 = (const float*)d_in[13];
    const float *Wproj = (const float*)d_in[14], *bproj = (const float*)d_in[15];
    const float *Wl1 = (const float*)d_in[16], *bl1 = (const float*)d_in[17];
    const float *Wl2 = (const float*)d_in[18], *bl2 = (const float*)d_in[19];
    float* out = (float*)d_out;

    float* scratch = nullptr;
    cudaGetSymbolAddress((void**)&scratch, g_scratch);
    float* P0 = scratch + OFF_P0;
    float* P1 = scratch + OFF_P1;
    float* P2 = scratch + OFF_P2;
    float* S0 = scratch + OFF_S0;
    float* S1 = scratch + OFF_S1;
    float* S2 = scratch + OFF_S2;
    float* dinvP = scratch + OFF_DP;   // dinvP/dinvS contiguous [NPROT+NSUB]
    float* dinvS = scratch + OFF_DS;
    float* Mp = scratch + OFF_MP;
    float* Ms = scratch + OFF_MS;
    float* cv = scratch + OFF_C;

    const int T = 256;
    const int gP = (NPROT + 63) / 64;
    const int gS = (NSUB + 63) / 64;
    const int scatP = (int)(((long)EPROT * 16 + T - 1) / T);
    const int scatS = (int)(((long)ESUB * 16 + T - 1) / T);

    // idx 0..2: setup (fused), so profiled launch idx 3 = protein conv1 GEMM
    k_fill1<<<(NPROT + NSUB + T - 1) / T, T>>>(dinvP, NPROT + NSUB);                 // 0
    k_count_both<<<(EPROT + ESUB + T - 1) / T, T>>>(ei_p + EPROT, ei_s + ESUB,
                                                    dinvP, dinvS);                   // 1
    k_rsqrt_prep<<<(NPROT + NSUB + T - 1) / T, T>>>(dinvP, Wproj, bproj, Wl1, bl1,
                                                    Mp, Ms, cv);                     // 2

    // ---- protein: conv1 -> scatter -> conv2(fold) -> scatter -> A-table(fold) ----
    k_gemm_n64<PDIM, false><<<gP, T>>>(x_p, Wp1, dinvP, nullptr, nullptr, P1, P2, NPROT); // 3 (profiled)
    k_scatter<<<scatP, T>>>(ei_p, ei_p + EPROT, EPROT, P1, P2);
    k_gemm_n64<HDIM, true><<<gP, T>>>(P2, Wp2, dinvP, dinvP, bp1, P1, P0, NPROT);
    k_scatter<<<scatP, T>>>(ei_p, ei_p + EPROT, EPROT, P1, P0);
    k_gemm_n64<HDIM, true><<<gP, T>>>(P0, Mp, nullptr, dinvP, bp2, P2, nullptr, NPROT);

    // ---- substrate ----
    k_gemm_n64<SDIM, false><<<gS, T>>>(x_s, Ws1, dinvS, nullptr, nullptr, S1, S2, NSUB);
    k_scatter<<<scatS, T>>>(ei_s, ei_s + ESUB, ESUB, S1, S2);
    k_gemm_n64<HDIM, true><<<gS, T>>>(S2, Ws2, dinvS, dinvS, bs1, S1, S0, NSUB);
    k_scatter<<<scatS, T>>>(ei_s, ei_s + ESUB, ESUB, S1, S0);
    k_gemm_n64<HDIM, true><<<gS, T>>>(S0, Ms, nullptr, dinvS, bs2, S2, nullptr, NSUB);

    // ---- link prediction: out[e] = relu(A[ep]+B[es]+c)@Wl2 + bl2 ----
    int linkBlocks = (int)(((long)(ELNK / 2) * 32 + T - 1) / T);
    k_link<<<linkBlocks, T>>>(ep, es, P2, S2, cv, Wl2, bl2, out);
}

// round 8
// speedup vs baseline: 1.3024x; 1.1261x over previous
#include <cuda_runtime.h>
#include <cuda_bf16.h>
#include <cstdint>

#define NPROT 100000
#define NSUB  50000
#define HDIM  64
#define PDIM  1024
#define SDIM  512
#define EPROT 3200000
#define ESUB  1600000
#define ELNK  2000000

// ---------------- scratch ----------------------------------------------------
#define OFF_P0 0L
#define OFF_P1 (OFF_P0 + (long)NPROT*64)
#define OFF_P2 (OFF_P1 + (long)NPROT*64)
#define OFF_S0 (OFF_P2 + (long)NPROT*64)
#define OFF_S1 (OFF_S0 + (long)NSUB*64)
#define OFF_S2 (OFF_S1 + (long)NSUB*64)
#define OFF_DP (OFF_S2 + (long)NSUB*64)
#define OFF_DS (OFF_DP + NPROT)
#define OFF_MP (OFF_DS + NSUB)
#define OFF_MS (OFF_MP + 64*64)
#define OFF_C  (OFF_MS + 64*64)
#define SCRATCH_TOTAL (OFF_C + 64)

__device__ __align__(256) float g_scratch[SCRATCH_TOTAL];

// ---------------- helpers ----------------------------------------------------
__device__ __forceinline__ uint32_t smem_u32(const void* p) {
    uint32_t a;
    asm("{ .reg .u64 t; cvta.to.shared.u64 t, %1; cvt.u32.u64 %0, t; }" : "=r"(a) : "l"(p));
    return a;
}
#define STS64(addr, val) \
    asm volatile("st.shared.b64 [%0], %1;" :: "r"((uint32_t)(addr)), "l"(val) : "memory")
#define STS128(r0, r1, r2, r3, addr) \
    asm volatile("st.shared.v4.b32 [%0], {%1, %2, %3, %4};" \
        :: "r"((uint32_t)(addr)), "r"(r0), "r"(r1), "r"(r2), "r"(r3) : "memory")
#define SMEM_SWIZZLE_128B(o) ((o) ^ (((o) >> 3) & 0x70))

#define LDSM_X4(r, addr) \
    asm volatile("ldmatrix.sync.aligned.m8n8.x4.shared.b16 {%0,%1,%2,%3}, [%4];" \
        : "=r"((r)[0]), "=r"((r)[1]), "=r"((r)[2]), "=r"((r)[3]) : "r"((uint32_t)(addr)))
#define LDSM_X2(r, addr) \
    asm volatile("ldmatrix.sync.aligned.m8n8.x2.shared.b16 {%0,%1}, [%2];" \
        : "=r"((r)[0]), "=r"((r)[1]) : "r"((uint32_t)(addr)))
#define MMA_BF16(d, a, b) \
    asm volatile("mma.sync.aligned.m16n8k16.row.col.f32.bf16.bf16.f32 " \
        "{%0,%1,%2,%3}, {%4,%5,%6,%7}, {%8,%9}, {%0,%1,%2,%3};" \
        : "+f"((d)[0]), "+f"((d)[1]), "+f"((d)[2]), "+f"((d)[3]) \
        : "r"((a)[0]), "r"((a)[1]), "r"((a)[2]), "r"((a)[3]), "r"((b)[0]), "r"((b)[1]))

__device__ __forceinline__ void split2(float a, float b, uint32_t& hi, uint32_t& lo) {
    __nv_bfloat16 ah = __float2bfloat16_rn(a);
    __nv_bfloat16 bh = __float2bfloat16_rn(b);
    float ar = a - __bfloat162float(ah);
    float br = b - __bfloat162float(bh);
    __nv_bfloat162 hv; hv.x = ah; hv.y = bh;
    __nv_bfloat162 lv; lv.x = __float2bfloat16_rn(ar); lv.y = __float2bfloat16_rn(br);
    hi = *(uint32_t*)&hv;
    lo = *(uint32_t*)&lv;
}

// ---------------- tensor-core conv1 GEMM: out[M,64] = (X @ W)*dinv -----------
// 128x64 CTA tile, 8 warps (warp = 16-row strip), bf16 hi/lo split, fp32 acc.
// D += Xh*Wh + Xh*Wl + Xl*Wh  (drop Xl*Wl, ~2^-18 relative)
template <int K>
__global__ void __launch_bounds__(256) k_gemm_tc(
        const float* __restrict__ X, const float* __restrict__ W,
        const float* __restrict__ dinv,
        float* __restrict__ outH, float* __restrict__ outAcc, int M) {
    __shared__ __align__(128) uint8_t smem[49152];
    const uint32_t sb = smem_u32(smem);
    const uint32_t AH = sb, AL = sb + 16384, BH = sb + 32768, BL = sb + 40960;
    const int tid = threadIdx.x;
    const int wid = tid >> 5;
    const int lane = tid & 31;
    const int row0 = blockIdx.x * 128;

    float d[8][4];
    #pragma unroll
    for (int nt = 0; nt < 8; nt++)
        #pragma unroll
        for (int j = 0; j < 4; j++) d[nt][j] = 0.f;

    for (int ch = 0; ch < K / 64; ch++) {
        const int kk = ch * 64;
        // ---- A: 128 rows x 64 k, fp32 -> bf16 hi/lo, SW128 rows of 128B ----
        #pragma unroll
        for (int it = 0; it < 8; it++) {
            int e = tid + (it << 8);
            int r = e >> 4;
            int c4 = (e & 15) << 2;
            float4 xv = make_float4(0.f, 0.f, 0.f, 0.f);
            if (row0 + r < M) xv = *(const float4*)&X[(long)(row0 + r) * K + kk + c4];
            uint32_t h0, l0, h1, l1;
            split2(xv.x, xv.y, h0, l0);
            split2(xv.z, xv.w, h1, l1);
            uint32_t sw = SMEM_SWIZZLE_128B((uint32_t)(r * 128 + (c4 << 1)));
            STS64(AH + sw, (uint64_t)h0 | ((uint64_t)h1 << 32));
            STS64(AL + sw, (uint64_t)l0 | ((uint64_t)l1 << 32));
        }
        // ---- B: Bs[n][k] = W[kk+k][n], 64x64 bf16 hi/lo, SW128 ----
        #pragma unroll
        for (int pass = 0; pass < 2; pass++) {
            int kb = (tid >> 6) + (pass << 2);   // 0..7
            int n  = tid & 63;
            int k0 = kb << 3;
            float v[8];
            #pragma unroll
            for (int j = 0; j < 8; j++) v[j] = W[(long)(kk + k0 + j) * 64 + n];
            uint32_t h[4], l[4];
            #pragma unroll
            for (int j = 0; j < 4; j++) split2(v[2 * j], v[2 * j + 1], h[j], l[j]);
            uint32_t sw = SMEM_SWIZZLE_128B((uint32_t)(n * 128 + (k0 << 1)));
            STS128(h[0], h[1], h[2], h[3], BH + sw);
            STS128(l[0], l[1], l[2], l[3], BL + sw);
        }
        __syncthreads();

        // ---- MMAs ----
        #pragma unroll
        for (int s = 0; s < 4; s++) {
            uint32_t aoff = SMEM_SWIZZLE_128B(
                (uint32_t)((wid * 16 + (lane & 15)) * 128 + s * 32 + ((lane >> 4) << 4)));
            uint32_t ah[4], al[4];
            LDSM_X4(ah, AH + aoff);
            LDSM_X4(al, AL + aoff);
            #pragma unroll
            for (int nt = 0; nt < 8; nt++) {
                uint32_t boff = SMEM_SWIZZLE_128B(
                    (uint32_t)((nt * 8 + (lane & 7)) * 128 + s * 32 + (((lane >> 3) & 1) << 4)));
                uint32_t bh[2], bl[2];
                LDSM_X2(bh, BH + boff);
                LDSM_X2(bl, BL + boff);
                MMA_BF16(d[nt], ah, bh);
                MMA_BF16(d[nt], ah, bl);
                MMA_BF16(d[nt], al, bh);
            }
        }
        __syncthreads();
    }

    // ---- epilogue ----
    int r0 = row0 + wid * 16 + (lane >> 2);
    int r1 = r0 + 8;
    int c0 = (lane & 3) << 1;
    bool ok0 = r0 < M, ok1 = r1 < M;
    float s0 = ok0 ? (dinv ? dinv[r0] : 1.0f) : 0.f;
    float s1 = ok1 ? (dinv ? dinv[r1] : 1.0f) : 0.f;
    #pragma unroll
    for (int nt = 0; nt < 8; nt++) {
        if (ok0) {
            float2 v = make_float2(d[nt][0] * s0, d[nt][1] * s0);
            long off = (long)r0 * 64 + nt * 8 + c0;
            *(float2*)&outH[off] = v;
            if (outAcc) *(float2*)&outAcc[off] = v;
        }
        if (ok1) {
            float2 v = make_float2(d[nt][2] * s1, d[nt][3] * s1);
            long off = (long)r1 * 64 + nt * 8 + c0;
            *(float2*)&outH[off] = v;
            if (outAcc) *(float2*)&outAcc[off] = v;
        }
    }
}

// ---------------- small kernels ---------------------------------------------
__global__ void k_fill1(float* p, int n) {
    int i = blockIdx.x * blockDim.x + threadIdx.x;
    if (i < n) p[i] = 1.0f;
}

__global__ void k_count_both(const int* __restrict__ dstP, const int* __restrict__ dstS,
                             float* __restrict__ degP, float* __restrict__ degS) {
    int i = blockIdx.x * blockDim.x + threadIdx.x;
    if (i < EPROT) atomicAdd(&degP[dstP[i]], 1.0f);
    else if (i < EPROT + ESUB) atomicAdd(&degS[dstS[i - EPROT]], 1.0f);
}

__global__ void k_rsqrt_prep(float* __restrict__ dinv,
                             const float* __restrict__ Wproj, const float* __restrict__ bproj,
                             const float* __restrict__ Wl1, const float* __restrict__ bl1,
                             float* __restrict__ Mp, float* __restrict__ Ms, float* __restrict__ c) {
    int gid = blockIdx.x * blockDim.x + threadIdx.x;
    if (gid < NPROT + NSUB) dinv[gid] = rsqrtf(dinv[gid]);
    if (gid < 128 * 64) {
        int a = gid >> 6, j = gid & 63;
        float s = 0.f;
        #pragma unroll 4
        for (int t = 0; t < 128; t++) s = fmaf(Wproj[a * 128 + t], Wl1[t * 64 + j], s);
        if (a < 64) Mp[a * 64 + j] = s;
        else        Ms[(a - 64) * 64 + j] = s;
    }
    if (gid < 64) {
        float s = bl1[gid];
        #pragma unroll 4
        for (int t = 0; t < 128; t++) s = fmaf(bproj[t], Wl1[t * 64 + gid], s);
        c[gid] = s;
    }
}

// ---------------- FFMA GEMM (K=64 convs): out = (f(X)@W)*dinvOut ------------
template <int K, bool FOLD>
__global__ void __launch_bounds__(256) k_gemm_n64(
        const float* __restrict__ X, const float* __restrict__ W,
        const float* __restrict__ dinvOut,
        const float* __restrict__ dinvIn, const float* __restrict__ biasIn,
        float* __restrict__ outH, float* __restrict__ outAcc, int M) {
    __shared__ float Xs[64][16];
    __shared__ float Ws[16][64];
    const int tid = threadIdx.x;
    const int tx = tid & 15;
    const int ty = tid >> 4;
    const int row0 = blockIdx.x * 64;

    float acc[4][4];
    #pragma unroll
    for (int i = 0; i < 4; i++)
        #pragma unroll
        for (int j = 0; j < 4; j++) acc[i][j] = 0.f;

    const int lr = tid >> 2;
    const int lc = (tid & 3) << 2;
    const int wr = tid >> 4;
    const int wc = (tid & 15) << 2;

    for (int kk = 0; kk < K; kk += 16) {
        float4 xv = make_float4(0.f, 0.f, 0.f, 0.f);
        if (row0 + lr < M) {
            xv = *(const float4*)&X[(long)(row0 + lr) * K + kk + lc];
            if (FOLD) {
                float di = dinvIn[row0 + lr];
                float4 bb = *(const float4*)&biasIn[kk + lc];
                xv = make_float4(fmaf(xv.x, di, bb.x), fmaf(xv.y, di, bb.y),
                                 fmaf(xv.z, di, bb.z), fmaf(xv.w, di, bb.w));
            }
        }
        *(float4*)&Xs[lr][lc] = xv;
        *(float4*)&Ws[wr][wc] = *(const float4*)&W[(long)(kk + wr) * 64 + wc];
        __syncthreads();
        #pragma unroll
        for (int k = 0; k < 16; k++) {
            float4 wv = *(const float4*)&Ws[k][tx << 2];
            float xr[4];
            #pragma unroll
            for (int i = 0; i < 4; i++) xr[i] = Xs[ty + (i << 4)][k];
            #pragma unroll
            for (int i = 0; i < 4; i++) {
                acc[i][0] = fmaf(xr[i], wv.x, acc[i][0]);
                acc[i][1] = fmaf(xr[i], wv.y, acc[i][1]);
                acc[i][2] = fmaf(xr[i], wv.z, acc[i][2]);
                acc[i][3] = fmaf(xr[i], wv.w, acc[i][3]);
            }
        }
        __syncthreads();
    }

    #pragma unroll
    for (int i = 0; i < 4; i++) {
        int r = row0 + ty + (i << 4);
        if (r < M) {
            float d = dinvOut ? dinvOut[r] : 1.0f;
            float4 v = make_float4(acc[i][0] * d, acc[i][1] * d, acc[i][2] * d, acc[i][3] * d);
            *(float4*)&outH[(long)r * 64 + (tx << 2)] = v;
            if (outAcc) *(float4*)&outAcc[(long)r * 64 + (tx << 2)] = v;
        }
    }
}

// ---------------- edge scatter ----------------------------------------------
__global__ void k_scatter(const int* __restrict__ src, const int* __restrict__ dst,
                          int E, const float* __restrict__ hs, float* __restrict__ acc) {
    int gid = blockIdx.x * blockDim.x + threadIdx.x;
    int e = gid >> 4;
    if (e >= E) return;
    int j = (gid & 15) << 2;
    int s = src[e];
    int d = dst[e];
    float4 v = *(const float4*)&hs[(long)s * 64 + j];
    float* addr = &acc[(long)d * 64 + j];
    asm volatile("red.global.add.v4.f32 [%0], {%1, %2, %3, %4};"
                 :: "l"(addr), "f"(v.x), "f"(v.y), "f"(v.z), "f"(v.w)
                 : "memory");
}

// ---------------- link predictor --------------------------------------------
__global__ void k_link(const int* __restrict__ ep, const int* __restrict__ es,
                       const float* __restrict__ A, const float* __restrict__ B,
                       const float* __restrict__ cvec, const float* __restrict__ wl2,
                       const float* __restrict__ bl2, float* __restrict__ out) {
    int lane = threadIdx.x & 31;
    int half = lane >> 4;
    int sub = lane & 15;
    int warp = (blockIdx.x * blockDim.x + threadIdx.x) >> 5;
    if (warp * 2 >= ELNK) return;
    int e = warp * 2 + half;

    float4 c4 = *(const float4*)&cvec[sub << 2];
    float4 w4 = *(const float4*)&wl2[sub << 2];

    long pi = (long)ep[e];
    long si = (long)es[e];
    float4 a = *(const float4*)&A[pi * 64 + (sub << 2)];
    float4 b = *(const float4*)&B[si * 64 + (sub << 2)];

    float r = fmaxf(a.x + b.x + c4.x, 0.f) * w4.x
            + fmaxf(a.y + b.y + c4.y, 0.f) * w4.y
            + fmaxf(a.z + b.z + c4.z, 0.f) * w4.z
            + fmaxf(a.w + b.w + c4.w, 0.f) * w4.w;

    #pragma unroll
    for (int off = 8; off > 0; off >>= 1)
        r += __shfl_down_sync(0xffffffffu, r, off, 16);

    if (sub == 0) out[e] = r + bl2[0];
}

// ---------------- launch ----------------------------------------------------
extern "C" void kernel_launch(void* const* d_in, const int* in_sizes, int n_in,
                              void* d_out, int out_size) {
    const float* x_p  = (const float*)d_in[0];
    const float* x_s  = (const float*)d_in[1];
    const int*   ei_p = (const int*)d_in[2];
    const int*   ei_s = (const int*)d_in[3];
    const int*   ep   = (const int*)d_in[4];
    const int*   es   = (const int*)d_in[5];
    const float *Wp1 = (const float*)d_in[6],  *bp1 = (const float*)d_in[7];
    const float *Ws1 = (const float*)d_in[8],  *bs1 = (const float*)d_in[9];
    const float *Wp2 = (const float*)d_in[10], *bp2 = (const float*)d_in[11];
    const float *Ws2 = (const float*)d_in[12], *bs2 = (const float*)d_in[13];
    const float *Wproj = (const float*)d_in[14], *bproj = (const float*)d_in[15];
    const float *Wl1 = (const float*)d_in[16], *bl1 = (const float*)d_in[17];
    const float *Wl2 = (const float*)d_in[18], *bl2 = (const float*)d_in[19];
    float* out = (float*)d_out;

    float* scratch = nullptr;
    cudaGetSymbolAddress((void**)&scratch, g_scratch);
    float* P0 = scratch + OFF_P0;
    float* P1 = scratch + OFF_P1;
    float* P2 = scratch + OFF_P2;
    float* S0 = scratch + OFF_S0;
    float* S1 = scratch + OFF_S1;
    float* S2 = scratch + OFF_S2;
    float* dinvP = scratch + OFF_DP;
    float* dinvS = scratch + OFF_DS;
    float* Mp = scratch + OFF_MP;
    float* Ms = scratch + OFF_MS;
    float* cv = scratch + OFF_C;

    const int T = 256;
    const int gP = (NPROT + 63) / 64;
    const int gS = (NSUB + 63) / 64;
    const int gPt = (NPROT + 127) / 128;
    const int gSt = (NSUB + 127) / 128;
    const int scatP = (int)(((long)EPROT * 16 + T - 1) / T);
    const int scatS = (int)(((long)ESUB * 16 + T - 1) / T);

    k_fill1<<<(NPROT + NSUB + T - 1) / T, T>>>(dinvP, NPROT + NSUB);                 // 0
    k_count_both<<<(EPROT + ESUB + T - 1) / T, T>>>(ei_p + EPROT, ei_s + ESUB,
                                                    dinvP, dinvS);                   // 1
    k_rsqrt_prep<<<(NPROT + NSUB + T - 1) / T, T>>>(dinvP, Wproj, bproj, Wl1, bl1,
                                                    Mp, Ms, cv);                     // 2

    // ---- protein ----
    k_gemm_tc<PDIM><<<gPt, T>>>(x_p, Wp1, dinvP, P1, P2, NPROT);                     // 3 (profiled)
    k_scatter<<<scatP, T>>>(ei_p, ei_p + EPROT, EPROT, P1, P2);
    k_gemm_n64<HDIM, true><<<gP, T>>>(P2, Wp2, dinvP, dinvP, bp1, P1, P0, NPROT);
    k_scatter<<<scatP, T>>>(ei_p, ei_p + EPROT, EPROT, P1, P0);
    k_gemm_n64<HDIM, true><<<gP, T>>>(P0, Mp, nullptr, dinvP, bp2, P2, nullptr, NPROT);

    // ---- substrate ----
    k_gemm_tc<SDIM><<<gSt, T>>>(x_s, Ws1, dinvS, S1, S2, NSUB);
    k_scatter<<<scatS, T>>>(ei_s, ei_s + ESUB, ESUB, S1, S2);
    k_gemm_n64<HDIM, true><<<gS, T>>>(S2, Ws2, dinvS, dinvS, bs1, S1, S0, NSUB);
    k_scatter<<<scatS, T>>>(ei_s, ei_s + ESUB, ESUB, S1, S0);
    k_gemm_n64<HDIM, true><<<gS, T>>>(S0, Ms, nullptr, dinvS, bs2, S2, nullptr, NSUB);

    // ---- link prediction ----
    int linkBlocks = (int)(((long)(ELNK / 2) * 32 + T - 1) / T);
    k_link<<<linkBlocks, T>>>(ep, es, P2, S2, cv, Wl2, bl2, out);
}

// round 9
// speedup vs baseline: 1.3169x; 1.0111x over previous
#include <cuda_runtime.h>
#include <cuda_bf16.h>
#include <cstdint>

#define NPROT 100000
#define NSUB  50000
#define HDIM  64
#define PDIM  1024
#define SDIM  512
#define EPROT 3200000
#define ESUB  1600000
#define ELNK  2000000

// ---------------- scratch ----------------------------------------------------
#define OFF_P0 0L
#define OFF_P1 (OFF_P0 + (long)NPROT*64)
#define OFF_P2 (OFF_P1 + (long)NPROT*64)
#define OFF_S0 (OFF_P2 + (long)NPROT*64)
#define OFF_S1 (OFF_S0 + (long)NSUB*64)
#define OFF_S2 (OFF_S1 + (long)NSUB*64)
#define OFF_DP (OFF_S2 + (long)NSUB*64)
#define OFF_DS (OFF_DP + NPROT)
#define OFF_MP (OFF_DS + NSUB)
#define OFF_MS (OFF_MP + 64*64)
#define OFF_C  (OFF_MS + 64*64)
#define SCRATCH_TOTAL (OFF_C + 64)

__device__ __align__(256) float g_scratch[SCRATCH_TOTAL];

// ---------------- helpers ----------------------------------------------------
__device__ __forceinline__ uint32_t smem_u32(const void* p) {
    uint32_t a;
    asm("{ .reg .u64 t; cvta.to.shared.u64 t, %1; cvt.u32.u64 %0, t; }" : "=r"(a) : "l"(p));
    return a;
}
#define STS64(addr, val) \
    asm volatile("st.shared.b64 [%0], %1;" :: "r"((uint32_t)(addr)), "l"(val) : "memory")
#define STS128(r0, r1, r2, r3, addr) \
    asm volatile("st.shared.v4.b32 [%0], {%1, %2, %3, %4};" \
        :: "r"((uint32_t)(addr)), "r"(r0), "r"(r1), "r"(r2), "r"(r3) : "memory")
#define SMEM_SWIZZLE_128B(o) ((o) ^ (((o) >> 3) & 0x70))

#define LDSM_X4(r, addr) \
    asm volatile("ldmatrix.sync.aligned.m8n8.x4.shared.b16 {%0,%1,%2,%3}, [%4];" \
        : "=r"((r)[0]), "=r"((r)[1]), "=r"((r)[2]), "=r"((r)[3]) : "r"((uint32_t)(addr)))
#define LDSM_X2(r, addr) \
    asm volatile("ldmatrix.sync.aligned.m8n8.x2.shared.b16 {%0,%1}, [%2];" \
        : "=r"((r)[0]), "=r"((r)[1]) : "r"((uint32_t)(addr)))
#define MMA_BF16(d, a, b) \
    asm volatile("mma.sync.aligned.m16n8k16.row.col.f32.bf16.bf16.f32 " \
        "{%0,%1,%2,%3}, {%4,%5,%6,%7}, {%8,%9}, {%0,%1,%2,%3};" \
        : "+f"((d)[0]), "+f"((d)[1]), "+f"((d)[2]), "+f"((d)[3]) \
        : "r"((a)[0]), "r"((a)[1]), "r"((a)[2]), "r"((a)[3]), "r"((b)[0]), "r"((b)[1]))

__device__ __forceinline__ void split2(float a, float b, uint32_t& hi, uint32_t& lo) {
    __nv_bfloat16 ah = __float2bfloat16_rn(a);
    __nv_bfloat16 bh = __float2bfloat16_rn(b);
    float ar = a - __bfloat162float(ah);
    float br = b - __bfloat162float(bh);
    __nv_bfloat162 hv; hv.x = ah; hv.y = bh;
    __nv_bfloat162 lv; lv.x = __float2bfloat16_rn(ar); lv.y = __float2bfloat16_rn(br);
    hi = *(uint32_t*)&hv;
    lo = *(uint32_t*)&lv;
}

// buffer layout within one 48KB stage: AH 16K | AL 16K | BH 8K | BL 8K
#define TCBUF 49152

// ---------------- tensor-core conv1 GEMM: out[M,64] = (X @ W)*dinv -----------
// 128x64 CTA tile, 8 warps, bf16 hi/lo split, fp32 acc, double-buffered smem,
// register-prefetch pipeline: fetch(ch+1) -> MMA(ch) -> stage(ch+1) -> sync.
template <int K>
__global__ void __launch_bounds__(256, 2) k_gemm_tc(
        const float* __restrict__ X, const float* __restrict__ W,
        const float* __restrict__ dinv,
        float* __restrict__ outH, float* __restrict__ outAcc, int M) {
    extern __shared__ __align__(128) uint8_t smem[];
    const uint32_t sb = smem_u32(smem);
    const int tid = threadIdx.x;
    const int wid = tid >> 5;
    const int lane = tid & 31;
    const int row0 = blockIdx.x * 128;

    float d[8][4];
    #pragma unroll
    for (int nt = 0; nt < 8; nt++)
        #pragma unroll
        for (int j = 0; j < 4; j++) d[nt][j] = 0.f;

    // per-thread fetch registers
    float4 xv[8];
    float wv[16];

    const int arow = tid >> 1;           // A row this thread loads (2 thr/row)
    const int acol = (tid & 1) << 3;     // 0 or 8 (8 floats)
    const int bn = tid & 63;             // B col (n)
    const int bk0 = (tid >> 6) << 3;     // B k base (0,8,16,24); +32 second pass

    auto fetch = [&](int ch) {
        const int kk = ch * 64;
        bool ok = row0 + arow < M;
        const float* xp = ok ? &X[(long)(row0 + arow) * K + kk + acol] : nullptr;
        #pragma unroll
        for (int q = 0; q < 2; q++) {
            #pragma unroll
            for (int j = 0; j < 4; j++)
                xv[q * 4 + j] = ok ? *(const float4*)(xp + q * 4 * 4 + j * 4)
                                   : make_float4(0.f, 0.f, 0.f, 0.f);
        }
        // wait: xp + q*16 floats? careful: xv[8] covers 32 floats? No: 8 float4 = 32 floats
        // but this thread only loads 16 floats (acol..acol+15). Use 4 float4.
    };
    // NOTE: A tile is 128x64 fp32 = 8192 floats; 256 threads -> 32 floats/thread.
    // Redefine: each thread loads one half-row of 32 floats = 8 float4.
    // arow = tid>>1 gives 128 rows x 2 threads, each 32 floats. acol = (tid&1)*32.
    (void)acol;

    const int acol32 = (tid & 1) << 5;   // 0 or 32 floats

    auto fetchA = [&](int ch) {
        const int kk = ch * 64;
        bool ok = row0 + arow < M;
        if (ok) {
            const float* xp = &X[(long)(row0 + arow) * K + kk + acol32];
            #pragma unroll
            for (int j = 0; j < 8; j++) xv[j] = *(const float4*)(xp + j * 4);
        } else {
            #pragma unroll
            for (int j = 0; j < 8; j++) xv[j] = make_float4(0.f, 0.f, 0.f, 0.f);
        }
    };
    auto fetchB = [&](int ch) {
        const int kk = ch * 64;
        #pragma unroll
        for (int pass = 0; pass < 2; pass++) {
            int k0 = bk0 + pass * 32;
            #pragma unroll
            for (int j = 0; j < 8; j++)
                wv[pass * 8 + j] = W[(long)(kk + k0 + j) * 64 + bn];
        }
    };
    auto stage = [&](int buf) {
        const uint32_t AH = sb + buf * TCBUF;
        const uint32_t AL = AH + 16384;
        const uint32_t BH = AH + 32768;
        const uint32_t BL = AH + 40960;
        // A: this thread owns row arow, float cols acol32..acol32+31
        #pragma unroll
        for (int j = 0; j < 8; j++) {
            uint32_t h0, l0, h1, l1;
            split2(xv[j].x, xv[j].y, h0, l0);
            split2(xv[j].z, xv[j].w, h1, l1);
            uint32_t sw = SMEM_SWIZZLE_128B((uint32_t)(arow * 128 + ((acol32 + j * 4) << 1)));
            STS64(AH + sw, (uint64_t)h0 | ((uint64_t)h1 << 32));
            STS64(AL + sw, (uint64_t)l0 | ((uint64_t)l1 << 32));
        }
        // B: Bs[n][k] layout, this thread owns n=bn, k = bk0..bk0+7 (+32 pass 2)
        #pragma unroll
        for (int pass = 0; pass < 2; pass++) {
            int k0 = bk0 + pass * 32;
            uint32_t h[4], l[4];
            #pragma unroll
            for (int j = 0; j < 4; j++)
                split2(wv[pass * 8 + 2 * j], wv[pass * 8 + 2 * j + 1], h[j], l[j]);
            uint32_t sw = SMEM_SWIZZLE_128B((uint32_t)(bn * 128 + (k0 << 1)));
            STS128(h[0], h[1], h[2], h[3], BH + sw);
            STS128(l[0], l[1], l[2], l[3], BL + sw);
        }
    };
    auto mma_chunk = [&](int buf) {
        const uint32_t AH = sb + buf * TCBUF;
        const uint32_t AL = AH + 16384;
        const uint32_t BH = AH + 32768;
        const uint32_t BL = AH + 40960;
        #pragma unroll
        for (int s = 0; s < 4; s++) {
            uint32_t aoff = SMEM_SWIZZLE_128B(
                (uint32_t)((wid * 16 + (lane & 15)) * 128 + s * 32 + ((lane >> 4) << 4)));
            uint32_t ah[4], al[4];
            LDSM_X4(ah, AH + aoff);
            LDSM_X4(al, AL + aoff);
            #pragma unroll
            for (int nt = 0; nt < 8; nt++) {
                uint32_t boff = SMEM_SWIZZLE_128B(
                    (uint32_t)((nt * 8 + (lane & 7)) * 128 + s * 32 + (((lane >> 3) & 1) << 4)));
                uint32_t bh[2], bl[2];
                LDSM_X2(bh, BH + boff);
                LDSM_X2(bl, BL + boff);
                MMA_BF16(d[nt], ah, bh);
                MMA_BF16(d[nt], ah, bl);
                MMA_BF16(d[nt], al, bh);
            }
        }
    };
    (void)fetch;

    const int NCH = K / 64;
    fetchA(0); fetchB(0);
    stage(0);
    __syncthreads();
    for (int ch = 0; ch < NCH; ch++) {
        if (ch + 1 < NCH) { fetchA(ch + 1); fetchB(ch + 1); }
        mma_chunk(ch & 1);
        if (ch + 1 < NCH) stage((ch + 1) & 1);
        __syncthreads();
    }

    // ---- epilogue ----
    int r0 = row0 + wid * 16 + (lane >> 2);
    int r1 = r0 + 8;
    int c0 = (lane & 3) << 1;
    bool ok0 = r0 < M, ok1 = r1 < M;
    float s0 = ok0 ? (dinv ? dinv[r0] : 1.0f) : 0.f;
    float s1 = ok1 ? (dinv ? dinv[r1] : 1.0f) : 0.f;
    #pragma unroll
    for (int nt = 0; nt < 8; nt++) {
        if (ok0) {
            float2 v = make_float2(d[nt][0] * s0, d[nt][1] * s0);
            long off = (long)r0 * 64 + nt * 8 + c0;
            *(float2*)&outH[off] = v;
            if (outAcc) *(float2*)&outAcc[off] = v;
        }
        if (ok1) {
            float2 v = make_float2(d[nt][2] * s1, d[nt][3] * s1);
            long off = (long)r1 * 64 + nt * 8 + c0;
            *(float2*)&outH[off] = v;
            if (outAcc) *(float2*)&outAcc[off] = v;
        }
    }
}

// ---------------- small kernels ---------------------------------------------
__global__ void k_fill1(float* p, int n) {
    int i = blockIdx.x * blockDim.x + threadIdx.x;
    if (i < n) p[i] = 1.0f;
}

__global__ void k_count_both(const int* __restrict__ dstP, const int* __restrict__ dstS,
                             float* __restrict__ degP, float* __restrict__ degS) {
    int i = blockIdx.x * blockDim.x + threadIdx.x;
    if (i < EPROT) atomicAdd(&degP[dstP[i]], 1.0f);
    else if (i < EPROT + ESUB) atomicAdd(&degS[dstS[i - EPROT]], 1.0f);
}

__global__ void k_rsqrt_prep(float* __restrict__ dinv,
                             const float* __restrict__ Wproj, const float* __restrict__ bproj,
                             const float* __restrict__ Wl1, const float* __restrict__ bl1,
                             float* __restrict__ Mp, float* __restrict__ Ms, float* __restrict__ c) {
    int gid = blockIdx.x * blockDim.x + threadIdx.x;
    if (gid < NPROT + NSUB) dinv[gid] = rsqrtf(dinv[gid]);
    if (gid < 128 * 64) {
        int a = gid >> 6, j = gid & 63;
        float s = 0.f;
        #pragma unroll 4
        for (int t = 0; t < 128; t++) s = fmaf(Wproj[a * 128 + t], Wl1[t * 64 + j], s);
        if (a < 64) Mp[a * 64 + j] = s;
        else        Ms[(a - 64) * 64 + j] = s;
    }
    if (gid < 64) {
        float s = bl1[gid];
        #pragma unroll 4
        for (int t = 0; t < 128; t++) s = fmaf(bproj[t], Wl1[t * 64 + gid], s);
        c[gid] = s;
    }
}

// ---------------- FFMA GEMM (K=64 convs): out = (f(X)@W)*dinvOut ------------
template <int K, bool FOLD>
__global__ void __launch_bounds__(256) k_gemm_n64(
        const float* __restrict__ X, const float* __restrict__ W,
        const float* __restrict__ dinvOut,
        const float* __restrict__ dinvIn, const float* __restrict__ biasIn,
        float* __restrict__ outH, float* __restrict__ outAcc, int M) {
    __shared__ float Xs[64][16];
    __shared__ float Ws[16][64];
    const int tid = threadIdx.x;
    const int tx = tid & 15;
    const int ty = tid >> 4;
    const int row0 = blockIdx.x * 64;

    float acc[4][4];
    #pragma unroll
    for (int i = 0; i < 4; i++)
        #pragma unroll
        for (int j = 0; j < 4; j++) acc[i][j] = 0.f;

    const int lr = tid >> 2;
    const int lc = (tid & 3) << 2;
    const int wr = tid >> 4;
    const int wc = (tid & 15) << 2;

    for (int kk = 0; kk < K; kk += 16) {
        float4 xv = make_float4(0.f, 0.f, 0.f, 0.f);
        if (row0 + lr < M) {
            xv = *(const float4*)&X[(long)(row0 + lr) * K + kk + lc];
            if (FOLD) {
                float di = dinvIn[row0 + lr];
                float4 bb = *(const float4*)&biasIn[kk + lc];
                xv = make_float4(fmaf(xv.x, di, bb.x), fmaf(xv.y, di, bb.y),
                                 fmaf(xv.z, di, bb.z), fmaf(xv.w, di, bb.w));
            }
        }
        *(float4*)&Xs[lr][lc] = xv;
        *(float4*)&Ws[wr][wc] = *(const float4*)&W[(long)(kk + wr) * 64 + wc];
        __syncthreads();
        #pragma unroll
        for (int k = 0; k < 16; k++) {
            float4 wv = *(const float4*)&Ws[k][tx << 2];
            float xr[4];
            #pragma unroll
            for (int i = 0; i < 4; i++) xr[i] = Xs[ty + (i << 4)][k];
            #pragma unroll
            for (int i = 0; i < 4; i++) {
                acc[i][0] = fmaf(xr[i], wv.x, acc[i][0]);
                acc[i][1] = fmaf(xr[i], wv.y, acc[i][1]);
                acc[i][2] = fmaf(xr[i], wv.z, acc[i][2]);
                acc[i][3] = fmaf(xr[i], wv.w, acc[i][3]);
            }
        }
        __syncthreads();
    }

    #pragma unroll
    for (int i = 0; i < 4; i++) {
        int r = row0 + ty + (i << 4);
        if (r < M) {
            float d = dinvOut ? dinvOut[r] : 1.0f;
            float4 v = make_float4(acc[i][0] * d, acc[i][1] * d, acc[i][2] * d, acc[i][3] * d);
            *(float4*)&outH[(long)r * 64 + (tx << 2)] = v;
            if (outAcc) *(float4*)&outAcc[(long)r * 64 + (tx << 2)] = v;
        }
    }
}

// ---------------- edge scatter ----------------------------------------------
__global__ void k_scatter(const int* __restrict__ src, const int* __restrict__ dst,
                          int E, const float* __restrict__ hs, float* __restrict__ acc) {
    int gid = blockIdx.x * blockDim.x + threadIdx.x;
    int e = gid >> 4;
    if (e >= E) return;
    int j = (gid & 15) << 2;
    int s = src[e];
    int d = dst[e];
    float4 v = *(const float4*)&hs[(long)s * 64 + j];
    float* addr = &acc[(long)d * 64 + j];
    asm volatile("red.global.add.v4.f32 [%0], {%1, %2, %3, %4};"
                 :: "l"(addr), "f"(v.x), "f"(v.y), "f"(v.z), "f"(v.w)
                 : "memory");
}

// ---------------- link predictor --------------------------------------------
__global__ void k_link(const int* __restrict__ ep, const int* __restrict__ es,
                       const float* __restrict__ A, const float* __restrict__ B,
                       const float* __restrict__ cvec, const float* __restrict__ wl2,
                       const float* __restrict__ bl2, float* __restrict__ out) {
    int lane = threadIdx.x & 31;
    int half = lane >> 4;
    int sub = lane & 15;
    int warp = (blockIdx.x * blockDim.x + threadIdx.x) >> 5;
    if (warp * 2 >= ELNK) return;
    int e = warp * 2 + half;

    float4 c4 = *(const float4*)&cvec[sub << 2];
    float4 w4 = *(const float4*)&wl2[sub << 2];

    long pi = (long)ep[e];
    long si = (long)es[e];
    float4 a = *(const float4*)&A[pi * 64 + (sub << 2)];
    float4 b = *(const float4*)&B[si * 64 + (sub << 2)];

    float r = fmaxf(a.x + b.x + c4.x, 0.f) * w4.x
            + fmaxf(a.y + b.y + c4.y, 0.f) * w4.y
            + fmaxf(a.z + b.z + c4.z, 0.f) * w4.z
            + fmaxf(a.w + b.w + c4.w, 0.f) * w4.w;

    #pragma unroll
    for (int off = 8; off > 0; off >>= 1)
        r += __shfl_down_sync(0xffffffffu, r, off, 16);

    if (sub == 0) out[e] = r + bl2[0];
}

// ---------------- launch ----------------------------------------------------
extern "C" void kernel_launch(void* const* d_in, const int* in_sizes, int n_in,
                              void* d_out, int out_size) {
    const float* x_p  = (const float*)d_in[0];
    const float* x_s  = (const float*)d_in[1];
    const int*   ei_p = (const int*)d_in[2];
    const int*   ei_s = (const int*)d_in[3];
    const int*   ep   = (const int*)d_in[4];
    const int*   es   = (const int*)d_in[5];
    const float *Wp1 = (const float*)d_in[6],  *bp1 = (const float*)d_in[7];
    const float *Ws1 = (const float*)d_in[8],  *bs1 = (const float*)d_in[9];
    const float *Wp2 = (const float*)d_in[10], *bp2 = (const float*)d_in[11];
    const float *Ws2 = (const float*)d_in[12], *bs2 = (const float*)d_in[13];
    const float *Wproj = (const float*)d_in[14], *bproj = (const float*)d_in[15];
    const float *Wl1 = (const float*)d_in[16], *bl1 = (const float*)d_in[17];
    const float *Wl2 = (const float*)d_in[18], *bl2 = (const float*)d_in[19];
    float* out = (float*)d_out;

    float* scratch = nullptr;
    cudaGetSymbolAddress((void**)&scratch, g_scratch);
    float* P0 = scratch + OFF_P0;
    float* P1 = scratch + OFF_P1;
    float* P2 = scratch + OFF_P2;
    float* S0 = scratch + OFF_S0;
    float* S1 = scratch + OFF_S1;
    float* S2 = scratch + OFF_S2;
    float* dinvP = scratch + OFF_DP;
    float* dinvS = scratch + OFF_DS;
    float* Mp = scratch + OFF_MP;
    float* Ms = scratch + OFF_MS;
    float* cv = scratch + OFF_C;

    const int TC_SMEM = 2 * TCBUF;   // 96KB double buffer
    cudaFuncSetAttribute(k_gemm_tc<PDIM>, cudaFuncAttributeMaxDynamicSharedMemorySize, TC_SMEM);
    cudaFuncSetAttribute(k_gemm_tc<SDIM>, cudaFuncAttributeMaxDynamicSharedMemorySize, TC_SMEM);

    const int T = 256;
    const int gP = (NPROT + 63) / 64;
    const int gS = (NSUB + 63) / 64;
    const int gPt = (NPROT + 127) / 128;
    const int gSt = (NSUB + 127) / 128;
    const int scatP = (int)(((long)EPROT * 16 + T - 1) / T);
    const int scatS = (int)(((long)ESUB * 16 + T - 1) / T);

    k_fill1<<<(NPROT + NSUB + T - 1) / T, T>>>(dinvP, NPROT + NSUB);                 // 0
    k_count_both<<<(EPROT + ESUB + T - 1) / T, T>>>(ei_p + EPROT, ei_s + ESUB,
                                                    dinvP, dinvS);                   // 1
    k_rsqrt_prep<<<(NPROT + NSUB + T - 1) / T, T>>>(dinvP, Wproj, bproj, Wl1, bl1,
                                                    Mp, Ms, cv);                     // 2

    // ---- protein ----
    k_gemm_tc<PDIM><<<gPt, T, TC_SMEM>>>(x_p, Wp1, dinvP, P1, P2, NPROT);            // 3 (profiled)
    k_scatter<<<scatP, T>>>(ei_p, ei_p + EPROT, EPROT, P1, P2);
    k_gemm_n64<HDIM, true><<<gP, T>>>(P2, Wp2, dinvP, dinvP, bp1, P1, P0, NPROT);
    k_scatter<<<scatP, T>>>(ei_p, ei_p + EPROT, EPROT, P1, P0);
    k_gemm_n64<HDIM, true><<<gP, T>>>(P0, Mp, nullptr, dinvP, bp2, P2, nullptr, NPROT);

    // ---- substrate ----
    k_gemm_tc<SDIM><<<gSt, T, TC_SMEM>>>(x_s, Ws1, dinvS, S1, S2, NSUB);
    k_scatter<<<scatS, T>>>(ei_s, ei_s + ESUB, ESUB, S1, S2);
    k_gemm_n64<HDIM, true><<<gS, T>>>(S2, Ws2, dinvS, dinvS, bs1, S1, S0, NSUB);
    k_scatter<<<scatS, T>>>(ei_s, ei_s + ESUB, ESUB, S1, S0);
    k_gemm_n64<HDIM, true><<<gS, T>>>(S0, Ms, nullptr, dinvS, bs2, S2, nullptr, NSUB);

    // ---- link prediction ----
    int linkBlocks = (int)(((long)(ELNK / 2) * 32 + T - 1) / T);
    k_link<<<linkBlocks, T>>>(ep, es, P2, S2, cv, Wl2, bl2, out);
}

// round 10
// speedup vs baseline: 1.5485x; 1.1758x over previous
#include <cuda_runtime.h>
#include <cuda_bf16.h>
#include <cstdint>

#define NPROT 100000
#define NSUB  50000
#define HDIM  64
#define PDIM  1024
#define SDIM  512
#define EPROT 3200000
#define ESUB  1600000
#define ELNK  2000000

// ---------------- scratch ----------------------------------------------------
#define OFF_P0 0L
#define OFF_P1 (OFF_P0 + (long)NPROT*64)
#define OFF_P2 (OFF_P1 + (long)NPROT*64)
#define OFF_S0 (OFF_P2 + (long)NPROT*64)
#define OFF_S1 (OFF_S0 + (long)NSUB*64)
#define OFF_S2 (OFF_S1 + (long)NSUB*64)
#define OFF_DP (OFF_S2 + (long)NSUB*64)
#define OFF_DS (OFF_DP + NPROT)
#define OFF_MP (OFF_DS + NSUB)
#define OFF_MS (OFF_MP + 64*64)
#define OFF_C  (OFF_MS + 64*64)
// int regions (indices into the float array, reinterpreted)
#define OFF_CNT  (OFF_C + 64)                  // NPROT+NSUB ints (P then S)
#define OFF_OFFP (OFF_CNT + NPROT + NSUB)      // NPROT+1
#define OFF_OFFS (OFF_OFFP + NPROT + 1)        // NSUB+1
#define OFF_CURP (OFF_OFFS + NSUB + 1)         // NPROT
#define OFF_CURS (OFF_CURP + NPROT)            // NSUB
#define OFF_CSRP (OFF_CURS + NSUB)             // EPROT
#define OFF_CSRS (OFF_CSRP + EPROT)            // ESUB
#define SCRATCH_TOTAL (OFF_CSRS + ESUB)

__device__ __align__(256) float g_scratch[SCRATCH_TOTAL];

// ---------------- helpers ----------------------------------------------------
__device__ __forceinline__ uint32_t smem_u32(const void* p) {
    uint32_t a;
    asm("{ .reg .u64 t; cvta.to.shared.u64 t, %1; cvt.u32.u64 %0, t; }" : "=r"(a) : "l"(p));
    return a;
}
#define STS64(addr, val) \
    asm volatile("st.shared.b64 [%0], %1;" :: "r"((uint32_t)(addr)), "l"(val) : "memory")
#define STS128(r0, r1, r2, r3, addr) \
    asm volatile("st.shared.v4.b32 [%0], {%1, %2, %3, %4};" \
        :: "r"((uint32_t)(addr)), "r"(r0), "r"(r1), "r"(r2), "r"(r3) : "memory")
#define SMEM_SWIZZLE_128B(o) ((o) ^ (((o) >> 3) & 0x70))

#define LDSM_X4(r, addr) \
    asm volatile("ldmatrix.sync.aligned.m8n8.x4.shared.b16 {%0,%1,%2,%3}, [%4];" \
        : "=r"((r)[0]), "=r"((r)[1]), "=r"((r)[2]), "=r"((r)[3]) : "r"((uint32_t)(addr)))
#define LDSM_X2(r, addr) \
    asm volatile("ldmatrix.sync.aligned.m8n8.x2.shared.b16 {%0,%1}, [%2];" \
        : "=r"((r)[0]), "=r"((r)[1]) : "r"((uint32_t)(addr)))
#define MMA_BF16(d, a, b) \
    asm volatile("mma.sync.aligned.m16n8k16.row.col.f32.bf16.bf16.f32 " \
        "{%0,%1,%2,%3}, {%4,%5,%6,%7}, {%8,%9}, {%0,%1,%2,%3};" \
        : "+f"((d)[0]), "+f"((d)[1]), "+f"((d)[2]), "+f"((d)[3]) \
        : "r"((a)[0]), "r"((a)[1]), "r"((a)[2]), "r"((a)[3]), "r"((b)[0]), "r"((b)[1]))

__device__ __forceinline__ void split2(float a, float b, uint32_t& hi, uint32_t& lo) {
    __nv_bfloat16 ah = __float2bfloat16_rn(a);
    __nv_bfloat16 bh = __float2bfloat16_rn(b);
    float ar = a - __bfloat162float(ah);
    float br = b - __bfloat162float(bh);
    __nv_bfloat162 hv; hv.x = ah; hv.y = bh;
    __nv_bfloat162 lv; lv.x = __float2bfloat16_rn(ar); lv.y = __float2bfloat16_rn(br);
    hi = *(uint32_t*)&hv;
    lo = *(uint32_t*)&lv;
}

#define TCBUF 49152

// ---------------- tensor-core conv1 GEMM: out[M,64] = (X @ W)*dinv -----------
template <int K>
__global__ void __launch_bounds__(256, 2) k_gemm_tc(
        const float* __restrict__ X, const float* __restrict__ W,
        const float* __restrict__ dinv,
        float* __restrict__ outH, int M) {
    extern __shared__ __align__(128) uint8_t smem[];
    const uint32_t sb = smem_u32(smem);
    const int tid = threadIdx.x;
    const int wid = tid >> 5;
    const int lane = tid & 31;
    const int row0 = blockIdx.x * 128;

    float d[8][4];
    #pragma unroll
    for (int nt = 0; nt < 8; nt++)
        #pragma unroll
        for (int j = 0; j < 4; j++) d[nt][j] = 0.f;

    float4 xv[8];
    float wv[16];

    const int arow = tid >> 1;
    const int acol32 = (tid & 1) << 5;
    const int bn = tid & 63;
    const int bk0 = (tid >> 6) << 3;

    auto fetchA = [&](int ch) {
        const int kk = ch * 64;
        bool ok = row0 + arow < M;
        if (ok) {
            const float* xp = &X[(long)(row0 + arow) * K + kk + acol32];
            #pragma unroll
            for (int j = 0; j < 8; j++) xv[j] = *(const float4*)(xp + j * 4);
        } else {
            #pragma unroll
            for (int j = 0; j < 8; j++) xv[j] = make_float4(0.f, 0.f, 0.f, 0.f);
        }
    };
    auto fetchB = [&](int ch) {
        const int kk = ch * 64;
        #pragma unroll
        for (int pass = 0; pass < 2; pass++) {
            int k0 = bk0 + pass * 32;
            #pragma unroll
            for (int j = 0; j < 8; j++)
                wv[pass * 8 + j] = W[(long)(kk + k0 + j) * 64 + bn];
        }
    };
    auto stage = [&](int buf) {
        const uint32_t AH = sb + buf * TCBUF;
        const uint32_t AL = AH + 16384;
        const uint32_t BH = AH + 32768;
        const uint32_t BL = AH + 40960;
        #pragma unroll
        for (int j = 0; j < 8; j++) {
            uint32_t h0, l0, h1, l1;
            split2(xv[j].x, xv[j].y, h0, l0);
            split2(xv[j].z, xv[j].w, h1, l1);
            uint32_t sw = SMEM_SWIZZLE_128B((uint32_t)(arow * 128 + ((acol32 + j * 4) << 1)));
            STS64(AH + sw, (uint64_t)h0 | ((uint64_t)h1 << 32));
            STS64(AL + sw, (uint64_t)l0 | ((uint64_t)l1 << 32));
        }
        #pragma unroll
        for (int pass = 0; pass < 2; pass++) {
            int k0 = bk0 + pass * 32;
            uint32_t h[4], l[4];
            #pragma unroll
            for (int j = 0; j < 4; j++)
                split2(wv[pass * 8 + 2 * j], wv[pass * 8 + 2 * j + 1], h[j], l[j]);
            uint32_t sw = SMEM_SWIZZLE_128B((uint32_t)(bn * 128 + (k0 << 1)));
            STS128(h[0], h[1], h[2], h[3], BH + sw);
            STS128(l[0], l[1], l[2], l[3], BL + sw);
        }
    };
    auto mma_chunk = [&](int buf) {
        const uint32_t AH = sb + buf * TCBUF;
        const uint32_t AL = AH + 16384;
        const uint32_t BH = AH + 32768;
        const uint32_t BL = AH + 40960;
        #pragma unroll
        for (int s = 0; s < 4; s++) {
            uint32_t aoff = SMEM_SWIZZLE_128B(
                (uint32_t)((wid * 16 + (lane & 15)) * 128 + s * 32 + ((lane >> 4) << 4)));
            uint32_t ah[4], al[4];
            LDSM_X4(ah, AH + aoff);
            LDSM_X4(al, AL + aoff);
            #pragma unroll
            for (int nt = 0; nt < 8; nt++) {
                uint32_t boff = SMEM_SWIZZLE_128B(
                    (uint32_t)((nt * 8 + (lane & 7)) * 128 + s * 32 + (((lane >> 3) & 1) << 4)));
                uint32_t bh[2], bl[2];
                LDSM_X2(bh, BH + boff);
                LDSM_X2(bl, BL + boff);
                MMA_BF16(d[nt], ah, bh);
                MMA_BF16(d[nt], ah, bl);
                MMA_BF16(d[nt], al, bh);
            }
        }
    };

    const int NCH = K / 64;
    fetchA(0); fetchB(0);
    stage(0);
    __syncthreads();
    for (int ch = 0; ch < NCH; ch++) {
        if (ch + 1 < NCH) { fetchA(ch + 1); fetchB(ch + 1); }
        mma_chunk(ch & 1);
        if (ch + 1 < NCH) stage((ch + 1) & 1);
        __syncthreads();
    }

    int r0 = row0 + wid * 16 + (lane >> 2);
    int r1 = r0 + 8;
    int c0 = (lane & 3) << 1;
    bool ok0 = r0 < M, ok1 = r1 < M;
    float s0 = ok0 ? (dinv ? dinv[r0] : 1.0f) : 0.f;
    float s1 = ok1 ? (dinv ? dinv[r1] : 1.0f) : 0.f;
    #pragma unroll
    for (int nt = 0; nt < 8; nt++) {
        if (ok0) {
            *(float2*)&outH[(long)r0 * 64 + nt * 8 + c0] =
                make_float2(d[nt][0] * s0, d[nt][1] * s0);
        }
        if (ok1) {
            *(float2*)&outH[(long)r1 * 64 + nt * 8 + c0] =
                make_float2(d[nt][2] * s1, d[nt][3] * s1);
        }
    }
}

// ---------------- CSR build --------------------------------------------------
__global__ void k_zero_cnt(int* cnt, int n) {
    int i = blockIdx.x * blockDim.x + threadIdx.x;
    if (i < n) cnt[i] = 0;
}

__global__ void k_count_int(const int* __restrict__ dstP, const int* __restrict__ dstS,
                            int* __restrict__ cntP, int* __restrict__ cntS) {
    int i = blockIdx.x * blockDim.x + threadIdx.x;
    if (i < EPROT) atomicAdd(&cntP[dstP[i]], 1);
    else if (i < EPROT + ESUB) atomicAdd(&cntS[dstS[i - EPROT]], 1);
}

// dinv = rsqrt(1 + cnt)  (cnt contiguous P then S), plus Wproj@Wl1 fold
__global__ void k_rsqrt_prep(const int* __restrict__ cnt, float* __restrict__ dinv,
                             const float* __restrict__ Wproj, const float* __restrict__ bproj,
                             const float* __restrict__ Wl1, const float* __restrict__ bl1,
                             float* __restrict__ Mp, float* __restrict__ Ms, float* __restrict__ c) {
    int gid = blockIdx.x * blockDim.x + threadIdx.x;
    if (gid < NPROT + NSUB) dinv[gid] = rsqrtf(1.0f + (float)cnt[gid]);
    if (gid < 128 * 64) {
        int a = gid >> 6, j = gid & 63;
        float s = 0.f;
        #pragma unroll 4
        for (int t = 0; t < 128; t++) s = fmaf(Wproj[a * 128 + t], Wl1[t * 64 + j], s);
        if (a < 64) Mp[a * 64 + j] = s;
        else        Ms[(a - 64) * 64 + j] = s;
    }
    if (gid < 64) {
        float s = bl1[gid];
        #pragma unroll 4
        for (int t = 0; t < 128; t++) s = fmaf(bproj[t], Wl1[t * 64 + gid], s);
        c[gid] = s;
    }
}

// block 0 scans protein counts, block 1 substrate. 1024 threads.
__global__ void k_scan(const int* __restrict__ cntP, const int* __restrict__ cntS,
                       int* __restrict__ offP, int* __restrict__ offS,
                       int* __restrict__ curP, int* __restrict__ curS) {
    const int N = (blockIdx.x == 0) ? NPROT : NSUB;
    const int* cnt = (blockIdx.x == 0) ? cntP : cntS;
    int* off = (blockIdx.x == 0) ? offP : offS;
    int* cur = (blockIdx.x == 0) ? curP : curS;
    __shared__ int ls[1024];
    int t = threadIdx.x;
    int chunk = (N + 1023) >> 10;
    int lo = t * chunk;
    int hi = min(lo + chunk, N);
    int s = 0;
    for (int i = lo; i < hi; i++) s += cnt[i];
    ls[t] = s;
    __syncthreads();
    for (int dd = 1; dd < 1024; dd <<= 1) {
        int v = (t >= dd) ? ls[t - dd] : 0;
        __syncthreads();
        ls[t] += v;
        __syncthreads();
    }
    int run = (t > 0) ? ls[t - 1] : 0;
    for (int i = lo; i < hi; i++) {
        off[i] = run;
        cur[i] = run;
        run += cnt[i];
    }
    if (t == 1023) off[N] = run;
}

__global__ void k_fill_csr(const int* __restrict__ srcP, const int* __restrict__ dstP,
                           const int* __restrict__ srcS, const int* __restrict__ dstS,
                           int* __restrict__ curP, int* __restrict__ curS,
                           int* __restrict__ csrP, int* __restrict__ csrS) {
    int i = blockIdx.x * blockDim.x + threadIdx.x;
    if (i < EPROT) {
        int pos = atomicAdd(&curP[dstP[i]], 1);
        csrP[pos] = srcP[i];
    } else if (i < EPROT + ESUB) {
        int j = i - EPROT;
        int pos = atomicAdd(&curS[dstS[j]], 1);
        csrS[pos] = srcS[j];
    }
}

// ---------------- CSR aggregate: Y[d] = dinv[d]*(Hs[d] + sum Hs[nbr]) -------
// half-warp per node, 2-way unrolled gathers for MLP
__global__ void __launch_bounds__(256) k_aggregate(
        const int* __restrict__ off, const int* __restrict__ csr,
        const float* __restrict__ dinv, const float* __restrict__ Hs,
        float* __restrict__ Y, int N) {
    int gid = blockIdx.x * blockDim.x + threadIdx.x;
    int d = gid >> 4;
    if (d >= N) return;
    int sub = gid & 15;
    const float4* H4 = (const float4*)Hs;
    float4 acc = H4[(long)d * 16 + sub];   // self (already dinv-scaled)
    int j = off[d], j1 = off[d + 1];
    for (; j + 1 < j1; j += 2) {
        int s0 = csr[j], s1 = csr[j + 1];
        float4 v0 = H4[(long)s0 * 16 + sub];
        float4 v1 = H4[(long)s1 * 16 + sub];
        acc.x += v0.x + v1.x; acc.y += v0.y + v1.y;
        acc.z += v0.z + v1.z; acc.w += v0.w + v1.w;
    }
    if (j < j1) {
        int s0 = csr[j];
        float4 v0 = H4[(long)s0 * 16 + sub];
        acc.x += v0.x; acc.y += v0.y; acc.z += v0.z; acc.w += v0.w;
    }
    float dd = dinv[d];
    ((float4*)Y)[(long)d * 16 + sub] =
        make_float4(acc.x * dd, acc.y * dd, acc.z * dd, acc.w * dd);
}

// ---------------- FFMA GEMM (K=64): out = ((X+bias) @ W) * dinvOut ----------
template <int K, bool FOLD>
__global__ void __launch_bounds__(256) k_gemm_n64(
        const float* __restrict__ X, const float* __restrict__ W,
        const float* __restrict__ dinvOut, const float* __restrict__ biasIn,
        float* __restrict__ outH, int M) {
    __shared__ float Xs[64][16];
    __shared__ float Ws[16][64];
    const int tid = threadIdx.x;
    const int tx = tid & 15;
    const int ty = tid >> 4;
    const int row0 = blockIdx.x * 64;

    float acc[4][4];
    #pragma unroll
    for (int i = 0; i < 4; i++)
        #pragma unroll
        for (int j = 0; j < 4; j++) acc[i][j] = 0.f;

    const int lr = tid >> 2;
    const int lc = (tid & 3) << 2;
    const int wr = tid >> 4;
    const int wc = (tid & 15) << 2;

    for (int kk = 0; kk < K; kk += 16) {
        float4 xv = make_float4(0.f, 0.f, 0.f, 0.f);
        if (row0 + lr < M) {
            xv = *(const float4*)&X[(long)(row0 + lr) * K + kk + lc];
            if (FOLD) {
                float4 bb = *(const float4*)&biasIn[kk + lc];
                xv = make_float4(xv.x + bb.x, xv.y + bb.y, xv.z + bb.z, xv.w + bb.w);
            }
        }
        *(float4*)&Xs[lr][lc] = xv;
        *(float4*)&Ws[wr][wc] = *(const float4*)&W[(long)(kk + wr) * 64 + wc];
        __syncthreads();
        #pragma unroll
        for (int k = 0; k < 16; k++) {
            float4 wv = *(const float4*)&Ws[k][tx << 2];
            float xr[4];
            #pragma unroll
            for (int i = 0; i < 4; i++) xr[i] = Xs[ty + (i << 4)][k];
            #pragma unroll
            for (int i = 0; i < 4; i++) {
                acc[i][0] = fmaf(xr[i], wv.x, acc[i][0]);
                acc[i][1] = fmaf(xr[i], wv.y, acc[i][1]);
                acc[i][2] = fmaf(xr[i], wv.z, acc[i][2]);
                acc[i][3] = fmaf(xr[i], wv.w, acc[i][3]);
            }
        }
        __syncthreads();
    }

    #pragma unroll
    for (int i = 0; i < 4; i++) {
        int r = row0 + ty + (i << 4);
        if (r < M) {
            float d = dinvOut ? dinvOut[r] : 1.0f;
            *(float4*)&outH[(long)r * 64 + (tx << 2)] =
                make_float4(acc[i][0] * d, acc[i][1] * d, acc[i][2] * d, acc[i][3] * d);
        }
    }
}

// ---------------- link predictor --------------------------------------------
__global__ void k_link(const int* __restrict__ ep, const int* __restrict__ es,
                       const float* __restrict__ A, const float* __restrict__ B,
                       const float* __restrict__ cvec, const float* __restrict__ wl2,
                       const float* __restrict__ bl2, float* __restrict__ out) {
    int lane = threadIdx.x & 31;
    int half = lane >> 4;
    int sub = lane & 15;
    int warp = (blockIdx.x * blockDim.x + threadIdx.x) >> 5;
    if (warp * 2 >= ELNK) return;
    int e = warp * 2 + half;

    float4 c4 = *(const float4*)&cvec[sub << 2];
    float4 w4 = *(const float4*)&wl2[sub << 2];

    long pi = (long)ep[e];
    long si = (long)es[e];
    float4 a = *(const float4*)&A[pi * 64 + (sub << 2)];
    float4 b = *(const float4*)&B[si * 64 + (sub << 2)];

    float r = fmaxf(a.x + b.x + c4.x, 0.f) * w4.x
            + fmaxf(a.y + b.y + c4.y, 0.f) * w4.y
            + fmaxf(a.z + b.z + c4.z, 0.f) * w4.z
            + fmaxf(a.w + b.w + c4.w, 0.f) * w4.w;

    #pragma unroll
    for (int off = 8; off > 0; off >>= 1)
        r += __shfl_down_sync(0xffffffffu, r, off, 16);

    if (sub == 0) out[e] = r + bl2[0];
}

// ---------------- launch ----------------------------------------------------
extern "C" void kernel_launch(void* const* d_in, const int* in_sizes, int n_in,
                              void* d_out, int out_size) {
    const float* x_p  = (const float*)d_in[0];
    const float* x_s  = (const float*)d_in[1];
    const int*   ei_p = (const int*)d_in[2];
    const int*   ei_s = (const int*)d_in[3];
    const int*   ep   = (const int*)d_in[4];
    const int*   es   = (const int*)d_in[5];
    const float *Wp1 = (const float*)d_in[6],  *bp1 = (const float*)d_in[7];
    const float *Ws1 = (const float*)d_in[8],  *bs1 = (const float*)d_in[9];
    const float *Wp2 = (const float*)d_in[10], *bp2 = (const float*)d_in[11];
    const float *Ws2 = (const float*)d_in[12], *bs2 = (const float*)d_in[13];
    const float *Wproj = (const float*)d_in[14], *bproj = (const float*)d_in[15];
    const float *Wl1 = (const float*)d_in[16], *bl1 = (const float*)d_in[17];
    const float *Wl2 = (const float*)d_in[18], *bl2 = (const float*)d_in[19];
    float* out = (float*)d_out;

    float* scratch = nullptr;
    cudaGetSymbolAddress((void**)&scratch, g_scratch);
    float* P0 = scratch + OFF_P0;
    float* P1 = scratch + OFF_P1;
    float* P2 = scratch + OFF_P2;
    float* S0 = scratch + OFF_S0;
    float* S1 = scratch + OFF_S1;
    float* S2 = scratch + OFF_S2;
    float* dinvP = scratch + OFF_DP;
    float* dinvS = scratch + OFF_DS;
    float* Mp = scratch + OFF_MP;
    float* Ms = scratch + OFF_MS;
    float* cv = scratch + OFF_C;
    int* cnt  = (int*)(scratch + OFF_CNT);     // P then S contiguous
    int* cntP = cnt;
    int* cntS = cnt + NPROT;
    int* offP = (int*)(scratch + OFF_OFFP);
    int* offS = (int*)(scratch + OFF_OFFS);
    int* curP = (int*)(scratch + OFF_CURP);
    int* curS = (int*)(scratch + OFF_CURS);
    int* csrP = (int*)(scratch + OFF_CSRP);
    int* csrS = (int*)(scratch + OFF_CSRS);

    const int TC_SMEM = 2 * TCBUF;
    cudaFuncSetAttribute(k_gemm_tc<PDIM>, cudaFuncAttributeMaxDynamicSharedMemorySize, TC_SMEM);
    cudaFuncSetAttribute(k_gemm_tc<SDIM>, cudaFuncAttributeMaxDynamicSharedMemorySize, TC_SMEM);

    const int T = 256;
    const int gP = (NPROT + 63) / 64;
    const int gS = (NSUB + 63) / 64;
    const int gPt = (NPROT + 127) / 128;
    const int gSt = (NSUB + 127) / 128;
    const int aggP = (int)(((long)NPROT * 16 + T - 1) / T);
    const int aggS = (int)(((long)NSUB * 16 + T - 1) / T);

    k_zero_cnt<<<(NPROT + NSUB + T - 1) / T, T>>>(cnt, NPROT + NSUB);                // 0
    k_count_int<<<(EPROT + ESUB + T - 1) / T, T>>>(ei_p + EPROT, ei_s + ESUB,
                                                   cntP, cntS);                      // 1
    k_rsqrt_prep<<<(NPROT + NSUB + T - 1) / T, T>>>(cnt, dinvP, Wproj, bproj,
                                                    Wl1, bl1, Mp, Ms, cv);           // 2
    // ---- protein conv1 GEMM (profiled, idx 3) ----
    k_gemm_tc<PDIM><<<gPt, T, TC_SMEM>>>(x_p, Wp1, dinvP, P1, NPROT);                // 3
    // ---- CSR build ----
    k_scan<<<2, 1024>>>(cntP, cntS, offP, offS, curP, curS);                         // 4
    k_fill_csr<<<(EPROT + ESUB + T - 1) / T, T>>>(ei_p, ei_p + EPROT,
                                                  ei_s, ei_s + ESUB,
                                                  curP, curS, csrP, csrS);           // 5
    // ---- protein chain ----
    k_aggregate<<<aggP, T>>>(offP, csrP, dinvP, P1, P2, NPROT);                      // 6
    k_gemm_n64<HDIM, true><<<gP, T>>>(P2, Wp2, dinvP, bp1, P1, NPROT);               // 7
    k_aggregate<<<aggP, T>>>(offP, csrP, dinvP, P1, P0, NPROT);                      // 8
    k_gemm_n64<HDIM, true><<<gP, T>>>(P0, Mp, nullptr, bp2, P2, NPROT);              // 9
    // ---- substrate chain ----
    k_gemm_tc<SDIM><<<gSt, T, TC_SMEM>>>(x_s, Ws1, dinvS, S1, NSUB);                 // 10
    k_aggregate<<<aggS, T>>>(offS, csrS, dinvS, S1, S2, NSUB);                       // 11
    k_gemm_n64<HDIM, true><<<gS, T>>>(S2, Ws2, dinvS, bs1, S1, NSUB);                // 12
    k_aggregate<<<aggS, T>>>(offS, csrS, dinvS, S1, S0, NSUB);                       // 13
    k_gemm_n64<HDIM, true><<<gS, T>>>(S0, Ms, nullptr, bs2, S2, NSUB);               // 14
    // ---- link prediction ----
    int linkBlocks = (int)(((long)(ELNK / 2) * 32 + T - 1) / T);
    k_link<<<linkBlocks, T>>>(ep, es, P2, S2, cv, Wl2, bl2, out);                    // 15
}

// round 13
// speedup vs baseline: 1.6303x; 1.0528x over previous
#include <cuda_runtime.h>
#include <cuda_bf16.h>
#include <cuda_fp16.h>
#include <cstdint>

#define NPROT 100000
#define NSUB  50000
#define HDIM  64
#define PDIM  1024
#define SDIM  512
#define EPROT 3200000
#define ESUB  1600000
#define ELNK  2000000

// ---------------- scratch ----------------------------------------------------
#define OFF_P0 0L
#define OFF_P1 (OFF_P0 + (long)NPROT*64)
#define OFF_P2 (OFF_P1 + (long)NPROT*64)
#define OFF_S0 (OFF_P2 + (long)NPROT*64)
#define OFF_S1 (OFF_S0 + (long)NSUB*64)
#define OFF_S2 (OFF_S1 + (long)NSUB*64)
#define OFF_DP (OFF_S2 + (long)NSUB*64)
#define OFF_DS (OFF_DP + NPROT)
#define OFF_MP (OFF_DS + NSUB)
#define OFF_MS (OFF_MP + 64*64)
#define OFF_C  (OFF_MS + 64*64)
#define OFF_CNT  (OFF_C + 64)
#define OFF_OFFP (OFF_CNT + NPROT + NSUB)
#define OFF_OFFS (OFF_OFFP + NPROT + 1)
#define OFF_CURP (OFF_OFFS + NSUB + 1)
#define OFF_CURS (OFF_CURP + NPROT)
#define OFF_CSRP (OFF_CURS + NSUB)
#define OFF_CSRS (OFF_CSRP + EPROT)
#define SCRATCH_TOTAL (OFF_CSRS + ESUB)

__device__ __align__(256) float g_scratch[SCRATCH_TOTAL];

// ---------------- helpers ----------------------------------------------------
__device__ __forceinline__ uint32_t smem_u32(const void* p) {
    uint32_t a;
    asm("{ .reg .u64 t; cvta.to.shared.u64 t, %1; cvt.u32.u64 %0, t; }" : "=r"(a) : "l"(p));
    return a;
}
#define STS64(addr, val) \
    asm volatile("st.shared.b64 [%0], %1;" :: "r"((uint32_t)(addr)), "l"(val) : "memory")
#define STS128(r0, r1, r2, r3, addr) \
    asm volatile("st.shared.v4.b32 [%0], {%1, %2, %3, %4};" \
        :: "r"((uint32_t)(addr)), "r"(r0), "r"(r1), "r"(r2), "r"(r3) : "memory")
#define SMEM_SWIZZLE_128B(o) ((o) ^ (((o) >> 3) & 0x70))

#define LDSM_X4(r, addr) \
    asm volatile("ldmatrix.sync.aligned.m8n8.x4.shared.b16 {%0,%1,%2,%3}, [%4];" \
        : "=r"((r)[0]), "=r"((r)[1]), "=r"((r)[2]), "=r"((r)[3]) : "r"((uint32_t)(addr)))
#define LDSM_X2(r, addr) \
    asm volatile("ldmatrix.sync.aligned.m8n8.x2.shared.b16 {%0,%1}, [%2];" \
        : "=r"((r)[0]), "=r"((r)[1]) : "r"((uint32_t)(addr)))
#define MMA_BF16(d, a, b) \
    asm volatile("mma.sync.aligned.m16n8k16.row.col.f32.bf16.bf16.f32 " \
        "{%0,%1,%2,%3}, {%4,%5,%6,%7}, {%8,%9}, {%0,%1,%2,%3};" \
        : "+f"((d)[0]), "+f"((d)[1]), "+f"((d)[2]), "+f"((d)[3]) \
        : "r"((a)[0]), "r"((a)[1]), "r"((a)[2]), "r"((a)[3]), "r"((b)[0]), "r"((b)[1]))

__device__ __forceinline__ void split2(float a, float b, uint32_t& hi, uint32_t& lo) {
    __nv_bfloat16 ah = __float2bfloat16_rn(a);
    __nv_bfloat16 bh = __float2bfloat16_rn(b);
    float ar = a - __bfloat162float(ah);
    float br = b - __bfloat162float(bh);
    __nv_bfloat162 hv; hv.x = ah; hv.y = bh;
    __nv_bfloat162 lv; lv.x = __float2bfloat16_rn(ar); lv.y = __float2bfloat16_rn(br);
    hi = *(uint32_t*)&hv;
    lo = *(uint32_t*)&lv;
}

#define TCBUF 49152

// ---------------- tensor-core conv1 GEMM: outH(fp16)[M,64] = (X@W)*dinv -----
template <int K>
__global__ void __launch_bounds__(256, 2) k_gemm_tc(
        const float* __restrict__ X, const float* __restrict__ W,
        const float* __restrict__ dinv,
        __half* __restrict__ outH, int M) {
    extern __shared__ __align__(128) uint8_t smem[];
    const uint32_t sb = smem_u32(smem);
    const int tid = threadIdx.x;
    const int wid = tid >> 5;
    const int lane = tid & 31;
    const int row0 = blockIdx.x * 128;

    float d[8][4];
    #pragma unroll
    for (int nt = 0; nt < 8; nt++)
        #pragma unroll
        for (int j = 0; j < 4; j++) d[nt][j] = 0.f;

    float4 xv[8];
    float wv[16];

    const int arow = tid >> 1;
    const int acol32 = (tid & 1) << 5;
    const int bn = tid & 63;
    const int bk0 = (tid >> 6) << 3;

    auto fetchA = [&](int ch) {
        const int kk = ch * 64;
        bool ok = row0 + arow < M;
        if (ok) {
            const float* xp = &X[(long)(row0 + arow) * K + kk + acol32];
            #pragma unroll
            for (int j = 0; j < 8; j++) xv[j] = *(const float4*)(xp + j * 4);
        } else {
            #pragma unroll
            for (int j = 0; j < 8; j++) xv[j] = make_float4(0.f, 0.f, 0.f, 0.f);
        }
    };
    auto fetchB = [&](int ch) {
        const int kk = ch * 64;
        #pragma unroll
        for (int pass = 0; pass < 2; pass++) {
            int k0 = bk0 + pass * 32;
            #pragma unroll
            for (int j = 0; j < 8; j++)
                wv[pass * 8 + j] = W[(long)(kk + k0 + j) * 64 + bn];
        }
    };
    auto stage = [&](int buf) {
        const uint32_t AH = sb + buf * TCBUF;
        const uint32_t AL = AH + 16384;
        const uint32_t BH = AH + 32768;
        const uint32_t BL = AH + 40960;
        #pragma unroll
        for (int j = 0; j < 8; j++) {
            uint32_t h0, l0, h1, l1;
            split2(xv[j].x, xv[j].y, h0, l0);
            split2(xv[j].z, xv[j].w, h1, l1);
            uint32_t sw = SMEM_SWIZZLE_128B((uint32_t)(arow * 128 + ((acol32 + j * 4) << 1)));
            STS64(AH + sw, (uint64_t)h0 | ((uint64_t)h1 << 32));
            STS64(AL + sw, (uint64_t)l0 | ((uint64_t)l1 << 32));
        }
        #pragma unroll
        for (int pass = 0; pass < 2; pass++) {
            int k0 = bk0 + pass * 32;
            uint32_t h[4], l[4];
            #pragma unroll
            for (int j = 0; j < 4; j++)
                split2(wv[pass * 8 + 2 * j], wv[pass * 8 + 2 * j + 1], h[j], l[j]);
            uint32_t sw = SMEM_SWIZZLE_128B((uint32_t)(bn * 128 + (k0 << 1)));
            STS128(h[0], h[1], h[2], h[3], BH + sw);
            STS128(l[0], l[1], l[2], l[3], BL + sw);
        }
    };
    auto mma_chunk = [&](int buf) {
        const uint32_t AH = sb + buf * TCBUF;
        const uint32_t AL = AH + 16384;
        const uint32_t BH = AH + 32768;
        const uint32_t BL = AH + 40960;
        #pragma unroll
        for (int s = 0; s < 4; s++) {
            uint32_t aoff = SMEM_SWIZZLE_128B(
                (uint32_t)((wid * 16 + (lane & 15)) * 128 + s * 32 + ((lane >> 4) << 4)));
            uint32_t ah[4], al[4];
            LDSM_X4(ah, AH + aoff);
            LDSM_X4(al, AL + aoff);
            #pragma unroll
            for (int nt = 0; nt < 8; nt++) {
                uint32_t boff = SMEM_SWIZZLE_128B(
                    (uint32_t)((nt * 8 + (lane & 7)) * 128 + s * 32 + (((lane >> 3) & 1) << 4)));
                uint32_t bh[2], bl[2];
                LDSM_X2(bh, BH + boff);
                LDSM_X2(bl, BL + boff);
                MMA_BF16(d[nt], ah, bh);
                MMA_BF16(d[nt], ah, bl);
                MMA_BF16(d[nt], al, bh);
            }
        }
    };

    const int NCH = K / 64;
    fetchA(0); fetchB(0);
    stage(0);
    __syncthreads();
    for (int ch = 0; ch < NCH; ch++) {
        if (ch + 1 < NCH) { fetchA(ch + 1); fetchB(ch + 1); }
        mma_chunk(ch & 1);
        if (ch + 1 < NCH) stage((ch + 1) & 1);
        __syncthreads();
    }

    int r0 = row0 + wid * 16 + (lane >> 2);
    int r1 = r0 + 8;
    int c0 = (lane & 3) << 1;
    bool ok0 = r0 < M, ok1 = r1 < M;
    float s0 = ok0 ? dinv[r0] : 0.f;
    float s1 = ok1 ? dinv[r1] : 0.f;
    #pragma unroll
    for (int nt = 0; nt < 8; nt++) {
        if (ok0)
            *(__half2*)&outH[(long)r0 * 64 + nt * 8 + c0] =
                __floats2half2_rn(d[nt][0] * s0, d[nt][1] * s0);
        if (ok1)
            *(__half2*)&outH[(long)r1 * 64 + nt * 8 + c0] =
                __floats2half2_rn(d[nt][2] * s1, d[nt][3] * s1);
    }
}

// ---------------- CSR build --------------------------------------------------
__global__ void k_zero_cnt(int* cnt, int n) {
    int i = blockIdx.x * blockDim.x + threadIdx.x;
    if (i < n) cnt[i] = 0;
}

__global__ void k_count_int(const int* __restrict__ dstP, const int* __restrict__ dstS,
                            int* __restrict__ cntP, int* __restrict__ cntS) {
    int i = blockIdx.x * blockDim.x + threadIdx.x;
    if (i < EPROT) atomicAdd(&cntP[dstP[i]], 1);
    else if (i < EPROT + ESUB) atomicAdd(&cntS[dstS[i - EPROT]], 1);
}

__global__ void k_rsqrt_prep(const int* __restrict__ cnt, float* __restrict__ dinv,
                             const float* __restrict__ Wproj, const float* __restrict__ bproj,
                             const float* __restrict__ Wl1, const float* __restrict__ bl1,
                             float* __restrict__ Mp, float* __restrict__ Ms, float* __restrict__ c) {
    int gid = blockIdx.x * blockDim.x + threadIdx.x;
    if (gid < NPROT + NSUB) dinv[gid] = rsqrtf(1.0f + (float)cnt[gid]);
    if (gid < 128 * 64) {
        int a = gid >> 6, j = gid & 63;
        float s = 0.f;
        #pragma unroll 4
        for (int t = 0; t < 128; t++) s = fmaf(Wproj[a * 128 + t], Wl1[t * 64 + j], s);
        if (a < 64) Mp[a * 64 + j] = s;
        else        Ms[(a - 64) * 64 + j] = s;
    }
    if (gid < 64) {
        float s = bl1[gid];
        #pragma unroll 4
        for (int t = 0; t < 128; t++) s = fmaf(bproj[t], Wl1[t * 64 + gid], s);
        c[gid] = s;
    }
}

__global__ void k_scan(const int* __restrict__ cntP, const int* __restrict__ cntS,
                       int* __restrict__ offP, int* __restrict__ offS,
                       int* __restrict__ curP, int* __restrict__ curS) {
    const int N = (blockIdx.x == 0) ? NPROT : NSUB;
    const int* cnt = (blockIdx.x == 0) ? cntP : cntS;
    int* off = (blockIdx.x == 0) ? offP : offS;
    int* cur = (blockIdx.x == 0) ? curP : curS;
    __shared__ int ls[1024];
    int t = threadIdx.x;
    int chunk = (N + 1023) >> 10;
    int lo = t * chunk;
    int hi = min(lo + chunk, N);
    int s = 0;
    for (int i = lo; i < hi; i++) s += cnt[i];
    ls[t] = s;
    __syncthreads();
    for (int dd = 1; dd < 1024; dd <<= 1) {
        int v = (t >= dd) ? ls[t - dd] : 0;
        __syncthreads();
        ls[t] += v;
        __syncthreads();
    }
    int run = (t > 0) ? ls[t - 1] : 0;
    for (int i = lo; i < hi; i++) {
        off[i] = run;
        cur[i] = run;
        run += cnt[i];
    }
    if (t == 1023) off[N] = run;
}

__global__ void k_fill_csr(const int* __restrict__ srcP, const int* __restrict__ dstP,
                           const int* __restrict__ srcS, const int* __restrict__ dstS,
                           int* __restrict__ curP, int* __restrict__ curS,
                           int* __restrict__ csrP, int* __restrict__ csrS) {
    int i = blockIdx.x * blockDim.x + threadIdx.x;
    if (i < EPROT) {
        int pos = atomicAdd(&curP[dstP[i]], 1);
        csrP[pos] = srcP[i];
    } else if (i < EPROT + ESUB) {
        int j = i - EPROT;
        int pos = atomicAdd(&curS[dstS[j]], 1);
        csrS[pos] = srcS[j];
    }
}

// ---------------- CSR aggregate (fp16 in, fp32 out) --------------------------
// Y[d] = dinv[d] * (Hs[d] + sum Hs[nbr]); 8 threads/node, 16B gathers
__device__ __forceinline__ void acc_u4(float* a, uint4 v) {
    const __half2* h = (const __half2*)&v;
    #pragma unroll
    for (int i = 0; i < 4; i++) {
        float2 f = __half22float2(h[i]);
        a[2 * i] += f.x;
        a[2 * i + 1] += f.y;
    }
}

__global__ void __launch_bounds__(256) k_aggregate(
        const int* __restrict__ off, const int* __restrict__ csr,
        const float* __restrict__ dinv, const __half* __restrict__ Hs,
        float* __restrict__ Y, int N) {
    int gid = blockIdx.x * blockDim.x + threadIdx.x;
    int d = gid >> 3;
    if (d >= N) return;
    int sub = gid & 7;
    const uint4* H8 = (const uint4*)Hs;   // 8 halves per uint4; 8 uint4 per row
    float acc[8] = {0.f, 0.f, 0.f, 0.f, 0.f, 0.f, 0.f, 0.f};
    acc_u4(acc, H8[(long)d * 8 + sub]);   // self (already dinv-scaled)
    int j = off[d], j1 = off[d + 1];
    for (; j + 1 < j1; j += 2) {
        int s0 = csr[j], s1 = csr[j + 1];
        uint4 v0 = H8[(long)s0 * 8 + sub];
        uint4 v1 = H8[(long)s1 * 8 + sub];
        acc_u4(acc, v0);
        acc_u4(acc, v1);
    }
    if (j < j1) acc_u4(acc, H8[(long)csr[j] * 8 + sub]);
    float dd = dinv[d];
    float* yp = &Y[(long)d * 64 + sub * 8];
    *(float4*)yp = make_float4(acc[0] * dd, acc[1] * dd, acc[2] * dd, acc[3] * dd);
    *(float4*)(yp + 4) = make_float4(acc[4] * dd, acc[5] * dd, acc[6] * dd, acc[7] * dd);
}

// ---------------- FFMA GEMM (K=64): outH(fp16) = ((X+bias)@W)*dinvOut -------
template <int K>
__global__ void __launch_bounds__(256) k_gemm_n64(
        const float* __restrict__ X, const float* __restrict__ W,
        const float* __restrict__ dinvOut, const float* __restrict__ biasIn,
        __half* __restrict__ outH, int M) {
    __shared__ float Xs[64][16];
    __shared__ float Ws[16][64];
    const int tid = threadIdx.x;
    const int tx = tid & 15;
    const int ty = tid >> 4;
    const int row0 = blockIdx.x * 64;

    float acc[4][4];
    #pragma unroll
    for (int i = 0; i < 4; i++)
        #pragma unroll
        for (int j = 0; j < 4; j++) acc[i][j] = 0.f;

    const int lr = tid >> 2;
    const int lc = (tid & 3) << 2;
    const int wr = tid >> 4;
    const int wc = (tid & 15) << 2;

    for (int kk = 0; kk < K; kk += 16) {
        float4 xv = make_float4(0.f, 0.f, 0.f, 0.f);
        if (row0 + lr < M) {
            xv = *(const float4*)&X[(long)(row0 + lr) * K + kk + lc];
            float4 bb = *(const float4*)&biasIn[kk + lc];
            xv = make_float4(xv.x + bb.x, xv.y + bb.y, xv.z + bb.z, xv.w + bb.w);
        }
        *(float4*)&Xs[lr][lc] = xv;
        *(float4*)&Ws[wr][wc] = *(const float4*)&W[(long)(kk + wr) * 64 + wc];
        __syncthreads();
        #pragma unroll
        for (int k = 0; k < 16; k++) {
            float4 wv = *(const float4*)&Ws[k][tx << 2];
            float xr[4];
            #pragma unroll
            for (int i = 0; i < 4; i++) xr[i] = Xs[ty + (i << 4)][k];
            #pragma unroll
            for (int i = 0; i < 4; i++) {
                acc[i][0] = fmaf(xr[i], wv.x, acc[i][0]);
                acc[i][1] = fmaf(xr[i], wv.y, acc[i][1]);
                acc[i][2] = fmaf(xr[i], wv.z, acc[i][2]);
                acc[i][3] = fmaf(xr[i], wv.w, acc[i][3]);
            }
        }
        __syncthreads();
    }

    #pragma unroll
    for (int i = 0; i < 4; i++) {
        int r = row0 + ty + (i << 4);
        if (r < M) {
            float d = dinvOut ? dinvOut[r] : 1.0f;
            __half2 h0 = __floats2half2_rn(acc[i][0] * d, acc[i][1] * d);
            __half2 h1 = __floats2half2_rn(acc[i][2] * d, acc[i][3] * d);
            uint2 u;
            u.x = *(uint32_t*)&h0;
            u.y = *(uint32_t*)&h1;
            *(uint2*)&outH[(long)r * 64 + (tx << 2)] = u;
        }
    }
}

// ---------------- link predictor (fp16 tables) -------------------------------
__global__ void k_link(const int* __restrict__ ep, const int* __restrict__ es,
                       const __half* __restrict__ A, const __half* __restrict__ B,
                       const float* __restrict__ cvec, const float* __restrict__ wl2,
                       const float* __restrict__ bl2, float* __restrict__ out) {
    int lane = threadIdx.x & 31;
    int half = lane >> 4;
    int sub = lane & 15;
    int warp = (blockIdx.x * blockDim.x + threadIdx.x) >> 5;
    if (warp * 2 >= ELNK) return;
    int e = warp * 2 + half;

    float4 c4 = *(const float4*)&cvec[sub << 2];
    float4 w4 = *(const float4*)&wl2[sub << 2];

    long pi = (long)ep[e];
    long si = (long)es[e];
    uint2 au = *(const uint2*)&A[pi * 64 + (sub << 2)];
    uint2 bu = *(const uint2*)&B[si * 64 + (sub << 2)];
    float2 a0 = __half22float2(*(__half2*)&au.x);
    float2 a1 = __half22float2(*(__half2*)&au.y);
    float2 b0 = __half22float2(*(__half2*)&bu.x);
    float2 b1 = __half22float2(*(__half2*)&bu.y);

    float r = fmaxf(a0.x + b0.x + c4.x, 0.f) * w4.x
            + fmaxf(a0.y + b0.y + c4.y, 0.f) * w4.y
            + fmaxf(a1.x + b1.x + c4.z, 0.f) * w4.z
            + fmaxf(a1.y + b1.y + c4.w, 0.f) * w4.w;

    #pragma unroll
    for (int off = 8; off > 0; off >>= 1)
        r += __shfl_down_sync(0xffffffffu, r, off, 16);

    if (sub == 0) out[e] = r + bl2[0];
}

// ---------------- launch ----------------------------------------------------
extern "C" void kernel_launch(void* const* d_in, const int* in_sizes, int n_in,
                              void* d_out, int out_size) {
    const float* x_p  = (const float*)d_in[0];
    const float* x_s  = (const float*)d_in[1];
    const int*   ei_p = (const int*)d_in[2];
    const int*   ei_s = (const int*)d_in[3];
    const int*   ep   = (const int*)d_in[4];
    const int*   es   = (const int*)d_in[5];
    const float *Wp1 = (const float*)d_in[6],  *bp1 = (const float*)d_in[7];
    const float *Ws1 = (const float*)d_in[8],  *bs1 = (const float*)d_in[9];
    const float *Wp2 = (const float*)d_in[10], *bp2 = (const float*)d_in[11];
    const float *Ws2 = (const float*)d_in[12], *bs2 = (const float*)d_in[13];
    const float *Wproj = (const float*)d_in[14], *bproj = (const float*)d_in[15];
    const float *Wl1 = (const float*)d_in[16], *bl1 = (const float*)d_in[17];
    const float *Wl2 = (const float*)d_in[18], *bl2 = (const float*)d_in[19];
    float* out = (float*)d_out;

    float* scratch = nullptr;
    cudaGetSymbolAddress((void**)&scratch, g_scratch);
    float* P0 = scratch + OFF_P0;
    __half* P1h = (__half*)(scratch + OFF_P1);
    float* P2 = scratch + OFF_P2;
    float* S0 = scratch + OFF_S0;
    __half* S1h = (__half*)(scratch + OFF_S1);
    float* S2 = scratch + OFF_S2;
    __half* P2h = (__half*)(scratch + OFF_P2);  // reused: table A (after P2 freed)
    __half* S2h = (__half*)(scratch + OFF_S2);  // reused: table B
    float* dinvP = scratch + OFF_DP;
    float* dinvS = scratch + OFF_DS;
    float* Mp = scratch + OFF_MP;
    float* Ms = scratch + OFF_MS;
    float* cv = scratch + OFF_C;
    int* cnt  = (int*)(scratch + OFF_CNT);
    int* cntP = cnt;
    int* cntS = cnt + NPROT;
    int* offP = (int*)(scratch + OFF_OFFP);
    int* offS = (int*)(scratch + OFF_OFFS);
    int* curP = (int*)(scratch + OFF_CURP);
    int* curS = (int*)(scratch + OFF_CURS);
    int* csrP = (int*)(scratch + OFF_CSRP);
    int* csrS = (int*)(scratch + OFF_CSRS);

    const int TC_SMEM = 2 * TCBUF;
    cudaFuncSetAttribute(k_gemm_tc<PDIM>, cudaFuncAttributeMaxDynamicSharedMemorySize, TC_SMEM);
    cudaFuncSetAttribute(k_gemm_tc<SDIM>, cudaFuncAttributeMaxDynamicSharedMemorySize, TC_SMEM);

    const int T = 256;
    const int gP = (NPROT + 63) / 64;
    const int gS = (NSUB + 63) / 64;
    const int gPt = (NPROT + 127) / 128;
    const int gSt = (NSUB + 127) / 128;
    const int aggP = (int)(((long)NPROT * 8 + T - 1) / T);
    const int aggS = (int)(((long)NSUB * 8 + T - 1) / T);

    k_zero_cnt<<<(NPROT + NSUB + T - 1) / T, T>>>(cnt, NPROT + NSUB);                // 0
    k_count_int<<<(EPROT + ESUB + T - 1) / T, T>>>(ei_p + EPROT, ei_s + ESUB,
                                                   cntP, cntS);                      // 1
    k_rsqrt_prep<<<(NPROT + NSUB + T - 1) / T, T>>>(cnt, dinvP, Wproj, bproj,
                                                    Wl1, bl1, Mp, Ms, cv);           // 2
    // ---- protein conv1 GEMM (profiled, idx 3 — control) ----
    k_gemm_tc<PDIM><<<gPt, T, TC_SMEM>>>(x_p, Wp1, dinvP, P1h, NPROT);               // 3
    // ---- CSR build ----
    k_scan<<<2, 1024>>>(cntP, cntS, offP, offS, curP, curS);                         // 4
    k_fill_csr<<<(EPROT + ESUB + T - 1) / T, T>>>(ei_p, ei_p + EPROT,
                                                  ei_s, ei_s + ESUB,
                                                  curP, curS, csrP, csrS);           // 5
    // ---- protein chain ----
    k_aggregate<<<aggP, T>>>(offP, csrP, dinvP, P1h, P2, NPROT);                     // 6
    k_gemm_n64<HDIM><<<gP, T>>>(P2, Wp2, dinvP, bp1, P1h, NPROT);                    // 7
    k_aggregate<<<aggP, T>>>(offP, csrP, dinvP, P1h, P0, NPROT);                     // 8
    k_gemm_n64<HDIM><<<gP, T>>>(P0, Mp, nullptr, bp2, P2h, NPROT);                   // 9
    // ---- substrate chain ----
    k_gemm_tc<SDIM><<<gSt, T, TC_SMEM>>>(x_s, Ws1, dinvS, S1h, NSUB);                // 10
    k_aggregate<<<aggS, T>>>(offS, csrS, dinvS, S1h, S2, NSUB);                      // 11
    k_gemm_n64<HDIM><<<gS, T>>>(S2, Ws2, dinvS, bs1, S1h, NSUB);                     // 12
    k_aggregate<<<aggS, T>>>(offS, csrS, dinvS, S1h, S0, NSUB);                      // 13
    k_gemm_n64<HDIM><<<gS, T>>>(S0, Ms, nullptr, bs2, S2h, NSUB);                    // 14
    // ---- link prediction ----
    int linkBlocks = (int)(((long)(ELNK / 2) * 32 + T - 1) / T);
    k_link<<<linkBlocks, T>>>(ep, es, P2h, S2h, cv, Wl2, bl2, out);                  // 15
}

// round 14
// speedup vs baseline: 1.7871x; 1.0962x over previous
#include <cuda_runtime.h>
#include <cuda_bf16.h>
#include <cuda_fp16.h>
#include <cstdint>

#define NPROT 100000
#define NSUB  50000
#define HDIM  64
#define PDIM  1024
#define SDIM  512
#define EPROT 3200000
#define ESUB  1600000
#define ELNK  2000000

// ---------------- scratch ----------------------------------------------------
#define OFF_P0 0L
#define OFF_P1 (OFF_P0 + (long)NPROT*64)
#define OFF_P2 (OFF_P1 + (long)NPROT*64)
#define OFF_S0 (OFF_P2 + (long)NPROT*64)
#define OFF_S1 (OFF_S0 + (long)NSUB*64)
#define OFF_S2 (OFF_S1 + (long)NSUB*64)
#define OFF_DP (OFF_S2 + (long)NSUB*64)
#define OFF_DS (OFF_DP + NPROT)
#define OFF_MP (OFF_DS + NSUB)
#define OFF_MS (OFF_MP + 64*64)
#define OFF_C  (OFF_MS + 64*64)
#define OFF_CNT  (OFF_C + 64)
#define OFF_OFFP (OFF_CNT + NPROT + NSUB)
#define OFF_OFFS (OFF_OFFP + NPROT + 1)
#define OFF_CURP (OFF_OFFS + NSUB + 1)
#define OFF_CURS (OFF_CURP + NPROT)
#define OFF_CSRP (OFF_CURS + NSUB)
#define OFF_CSRS (OFF_CSRP + EPROT)
#define SCRATCH_TOTAL (OFF_CSRS + ESUB)

__device__ __align__(256) float g_scratch[SCRATCH_TOTAL];

// ---------------- helpers ----------------------------------------------------
__device__ __forceinline__ uint32_t smem_u32(const void* p) {
    uint32_t a;
    asm("{ .reg .u64 t; cvta.to.shared.u64 t, %1; cvt.u32.u64 %0, t; }" : "=r"(a) : "l"(p));
    return a;
}
#define STS128(r0, r1, r2, r3, addr) \
    asm volatile("st.shared.v4.b32 [%0], {%1, %2, %3, %4};" \
        :: "r"((uint32_t)(addr)), "r"(r0), "r"(r1), "r"(r2), "r"(r3) : "memory")
#define SMEM_SWIZZLE_128B(o) ((o) ^ (((o) >> 3) & 0x70))

#define LDSM_X2(r, addr) \
    asm volatile("ldmatrix.sync.aligned.m8n8.x2.shared.b16 {%0,%1}, [%2];" \
        : "=r"((r)[0]), "=r"((r)[1]) : "r"((uint32_t)(addr)))
#define MMA_BF16(d, a, b) \
    asm volatile("mma.sync.aligned.m16n8k16.row.col.f32.bf16.bf16.f32 " \
        "{%0,%1,%2,%3}, {%4,%5,%6,%7}, {%8,%9}, {%0,%1,%2,%3};" \
        : "+f"((d)[0]), "+f"((d)[1]), "+f"((d)[2]), "+f"((d)[3]) \
        : "r"((a)[0]), "r"((a)[1]), "r"((a)[2]), "r"((a)[3]), "r"((b)[0]), "r"((b)[1]))

__device__ __forceinline__ void split2(float a, float b, uint32_t& hi, uint32_t& lo) {
    __nv_bfloat16 ah = __float2bfloat16_rn(a);
    __nv_bfloat16 bh = __float2bfloat16_rn(b);
    float ar = a - __bfloat162float(ah);
    float br = b - __bfloat162float(bh);
    __nv_bfloat162 hv; hv.x = ah; hv.y = bh;
    __nv_bfloat162 lv; lv.x = __float2bfloat16_rn(ar); lv.y = __float2bfloat16_rn(br);
    hi = *(uint32_t*)&hv;
    lo = *(uint32_t*)&lv;
}

// B-only smem buffer: BH 8K | BL 8K per stage, double buffered = 32 KB
#define TCBUF 16384

// ---------------- tensor-core conv1 GEMM: outH(fp16)[M,64] = (X@W)*dinv -----
// A fragments loaded straight from gmem (warp owns its 16 rows); B staged in
// smem (reused by all warps), hi/lo bf16 split, fp32 acc.
template <int K>
__global__ void __launch_bounds__(256, 2) k_gemm_tc(
        const float* __restrict__ X, const float* __restrict__ W,
        const float* __restrict__ dinv,
        __half* __restrict__ outH, int M) {
    extern __shared__ __align__(128) uint8_t smem[];
    const uint32_t sb = smem_u32(smem);
    const int tid = threadIdx.x;
    const int wid = tid >> 5;
    const int lane = tid & 31;
    const int row0 = blockIdx.x * 128;

    float d[8][4];
    #pragma unroll
    for (int nt = 0; nt < 8; nt++)
        #pragma unroll
        for (int j = 0; j < 4; j++) d[nt][j] = 0.f;

    float wv[16];

    // B staging ownership
    const int bn = tid & 63;
    const int bk0 = (tid >> 6) << 3;

    // A fragment coordinates for this thread
    const int ar0 = row0 + wid * 16 + (lane >> 2);
    const int ar1 = ar0 + 8;
    const int ak = (lane & 3) << 1;
    const bool okA0 = ar0 < M;
    const bool okA1 = ar1 < M;
    const float* xr0 = &X[(long)ar0 * K];
    const float* xr1 = &X[(long)ar1 * K];

    auto fetchB = [&](int ch) {
        const int kk = ch * 64;
        #pragma unroll
        for (int pass = 0; pass < 2; pass++) {
            int k0 = bk0 + pass * 32;
            #pragma unroll
            for (int j = 0; j < 8; j++)
                wv[pass * 8 + j] = W[(long)(kk + k0 + j) * 64 + bn];
        }
    };
    auto stageB = [&](int buf) {
        const uint32_t BH = sb + buf * TCBUF;
        const uint32_t BL = BH + 8192;
        #pragma unroll
        for (int pass = 0; pass < 2; pass++) {
            int k0 = bk0 + pass * 32;
            uint32_t h[4], l[4];
            #pragma unroll
            for (int j = 0; j < 4; j++)
                split2(wv[pass * 8 + 2 * j], wv[pass * 8 + 2 * j + 1], h[j], l[j]);
            uint32_t sw = SMEM_SWIZZLE_128B((uint32_t)(bn * 128 + (k0 << 1)));
            STS128(h[0], h[1], h[2], h[3], BH + sw);
            STS128(l[0], l[1], l[2], l[3], BL + sw);
        }
    };
    auto loadA = [&](int ch, int s, float2* av) {
        const int kk = ch * 64 + s * 16 + ak;
        if (okA0) {
            av[0] = *(const float2*)(xr0 + kk);
            av[2] = *(const float2*)(xr0 + kk + 8);
        } else {
            av[0] = make_float2(0.f, 0.f);
            av[2] = make_float2(0.f, 0.f);
        }
        if (okA1) {
            av[1] = *(const float2*)(xr1 + kk);
            av[3] = *(const float2*)(xr1 + kk + 8);
        } else {
            av[1] = make_float2(0.f, 0.f);
            av[3] = make_float2(0.f, 0.f);
        }
    };

    const int NCH = K / 64;
    fetchB(0);
    stageB(0);
    __syncthreads();

    float2 av[4], avn[4];
    loadA(0, 0, av);

    for (int ch = 0; ch < NCH; ch++) {
        if (ch + 1 < NCH) fetchB(ch + 1);
        const uint32_t BH = sb + (ch & 1) * TCBUF;
        const uint32_t BL = BH + 8192;
        #pragma unroll
        for (int s = 0; s < 4; s++) {
            if (s < 3) loadA(ch, s + 1, avn);
            else if (ch + 1 < NCH) loadA(ch + 1, 0, avn);
            uint32_t ah[4], al[4];
            split2(av[0].x, av[0].y, ah[0], al[0]);
            split2(av[1].x, av[1].y, ah[1], al[1]);
            split2(av[2].x, av[2].y, ah[2], al[2]);
            split2(av[3].x, av[3].y, ah[3], al[3]);
            #pragma unroll
            for (int nt = 0; nt < 8; nt++) {
                uint32_t boff = SMEM_SWIZZLE_128B(
                    (uint32_t)((nt * 8 + (lane & 7)) * 128 + s * 32 + (((lane >> 3) & 1) << 4)));
                uint32_t bh[2], bl[2];
                LDSM_X2(bh, BH + boff);
                LDSM_X2(bl, BL + boff);
                MMA_BF16(d[nt], ah, bh);
                MMA_BF16(d[nt], ah, bl);
                MMA_BF16(d[nt], al, bh);
            }
            av[0] = avn[0]; av[1] = avn[1]; av[2] = avn[2]; av[3] = avn[3];
        }
        if (ch + 1 < NCH) stageB((ch + 1) & 1);
        __syncthreads();
    }

    int r0 = row0 + wid * 16 + (lane >> 2);
    int r1 = r0 + 8;
    int c0 = (lane & 3) << 1;
    bool ok0 = r0 < M, ok1 = r1 < M;
    float s0 = ok0 ? dinv[r0] : 0.f;
    float s1 = ok1 ? dinv[r1] : 0.f;
    #pragma unroll
    for (int nt = 0; nt < 8; nt++) {
        if (ok0)
            *(__half2*)&outH[(long)r0 * 64 + nt * 8 + c0] =
                __floats2half2_rn(d[nt][0] * s0, d[nt][1] * s0);
        if (ok1)
            *(__half2*)&outH[(long)r1 * 64 + nt * 8 + c0] =
                __floats2half2_rn(d[nt][2] * s1, d[nt][3] * s1);
    }
}

// ---------------- CSR build --------------------------------------------------
__global__ void k_zero_cnt(int* cnt, int n) {
    int i = blockIdx.x * blockDim.x + threadIdx.x;
    if (i < n) cnt[i] = 0;
}

__global__ void k_count_int(const int* __restrict__ dstP, const int* __restrict__ dstS,
                            int* __restrict__ cntP, int* __restrict__ cntS) {
    int i = blockIdx.x * blockDim.x + threadIdx.x;
    if (i < EPROT) atomicAdd(&cntP[dstP[i]], 1);
    else if (i < EPROT + ESUB) atomicAdd(&cntS[dstS[i - EPROT]], 1);
}

__global__ void k_rsqrt_prep(const int* __restrict__ cnt, float* __restrict__ dinv,
                             const float* __restrict__ Wproj, const float* __restrict__ bproj,
                             const float* __restrict__ Wl1, const float* __restrict__ bl1,
                             float* __restrict__ Mp, float* __restrict__ Ms, float* __restrict__ c) {
    int gid = blockIdx.x * blockDim.x + threadIdx.x;
    if (gid < NPROT + NSUB) dinv[gid] = rsqrtf(1.0f + (float)cnt[gid]);
    if (gid < 128 * 64) {
        int a = gid >> 6, j = gid & 63;
        float s = 0.f;
        #pragma unroll 4
        for (int t = 0; t < 128; t++) s = fmaf(Wproj[a * 128 + t], Wl1[t * 64 + j], s);
        if (a < 64) Mp[a * 64 + j] = s;
        else        Ms[(a - 64) * 64 + j] = s;
    }
    if (gid < 64) {
        float s = bl1[gid];
        #pragma unroll 4
        for (int t = 0; t < 128; t++) s = fmaf(bproj[t], Wl1[t * 64 + gid], s);
        c[gid] = s;
    }
}

__global__ void k_scan(const int* __restrict__ cntP, const int* __restrict__ cntS,
                       int* __restrict__ offP, int* __restrict__ offS,
                       int* __restrict__ curP, int* __restrict__ curS) {
    const int N = (blockIdx.x == 0) ? NPROT : NSUB;
    const int* cnt = (blockIdx.x == 0) ? cntP : cntS;
    int* off = (blockIdx.x == 0) ? offP : offS;
    int* cur = (blockIdx.x == 0) ? curP : curS;
    __shared__ int ls[1024];
    int t = threadIdx.x;
    int chunk = (N + 1023) >> 10;
    int lo = t * chunk;
    int hi = min(lo + chunk, N);
    int s = 0;
    for (int i = lo; i < hi; i++) s += cnt[i];
    ls[t] = s;
    __syncthreads();
    for (int dd = 1; dd < 1024; dd <<= 1) {
        int v = (t >= dd) ? ls[t - dd] : 0;
        __syncthreads();
        ls[t] += v;
        __syncthreads();
    }
    int run = (t > 0) ? ls[t - 1] : 0;
    for (int i = lo; i < hi; i++) {
        off[i] = run;
        cur[i] = run;
        run += cnt[i];
    }
    if (t == 1023) off[N] = run;
}

__global__ void k_fill_csr(const int* __restrict__ srcP, const int* __restrict__ dstP,
                           const int* __restrict__ srcS, const int* __restrict__ dstS,
                           int* __restrict__ curP, int* __restrict__ curS,
                           int* __restrict__ csrP, int* __restrict__ csrS) {
    int i = blockIdx.x * blockDim.x + threadIdx.x;
    if (i < EPROT) {
        int pos = atomicAdd(&curP[dstP[i]], 1);
        csrP[pos] = srcP[i];
    } else if (i < EPROT + ESUB) {
        int j = i - EPROT;
        int pos = atomicAdd(&curS[dstS[j]], 1);
        csrS[pos] = srcS[j];
    }
}

// ---------------- CSR aggregate (fp16 in, fp32 out) --------------------------
__device__ __forceinline__ void acc_u4(float* a, uint4 v) {
    const __half2* h = (const __half2*)&v;
    #pragma unroll
    for (int i = 0; i < 4; i++) {
        float2 f = __half22float2(h[i]);
        a[2 * i] += f.x;
        a[2 * i + 1] += f.y;
    }
}

__global__ void __launch_bounds__(256) k_aggregate(
        const int* __restrict__ off, const int* __restrict__ csr,
        const float* __restrict__ dinv, const __half* __restrict__ Hs,
        float* __restrict__ Y, int N) {
    int gid = blockIdx.x * blockDim.x + threadIdx.x;
    int d = gid >> 3;
    if (d >= N) return;
    int sub = gid & 7;
    const uint4* H8 = (const uint4*)Hs;
    float acc[8] = {0.f, 0.f, 0.f, 0.f, 0.f, 0.f, 0.f, 0.f};
    acc_u4(acc, H8[(long)d * 8 + sub]);
    int j = off[d], j1 = off[d + 1];
    for (; j + 1 < j1; j += 2) {
        int s0 = csr[j], s1 = csr[j + 1];
        uint4 v0 = H8[(long)s0 * 8 + sub];
        uint4 v1 = H8[(long)s1 * 8 + sub];
        acc_u4(acc, v0);
        acc_u4(acc, v1);
    }
    if (j < j1) acc_u4(acc, H8[(long)csr[j] * 8 + sub]);
    float dd = dinv[d];
    float* yp = &Y[(long)d * 64 + sub * 8];
    *(float4*)yp = make_float4(acc[0] * dd, acc[1] * dd, acc[2] * dd, acc[3] * dd);
    *(float4*)(yp + 4) = make_float4(acc[4] * dd, acc[5] * dd, acc[6] * dd, acc[7] * dd);
}

// ---------------- FFMA GEMM (K=64): outH(fp16) = ((X+bias)@W)*dinvOut -------
template <int K>
__global__ void __launch_bounds__(256) k_gemm_n64(
        const float* __restrict__ X, const float* __restrict__ W,
        const float* __restrict__ dinvOut, const float* __restrict__ biasIn,
        __half* __restrict__ outH, int M) {
    __shared__ float Xs[64][16];
    __shared__ float Ws[16][64];
    const int tid = threadIdx.x;
    const int tx = tid & 15;
    const int ty = tid >> 4;
    const int row0 = blockIdx.x * 64;

    float acc[4][4];
    #pragma unroll
    for (int i = 0; i < 4; i++)
        #pragma unroll
        for (int j = 0; j < 4; j++) acc[i][j] = 0.f;

    const int lr = tid >> 2;
    const int lc = (tid & 3) << 2;
    const int wr = tid >> 4;
    const int wc = (tid & 15) << 2;

    for (int kk = 0; kk < K; kk += 16) {
        float4 xv = make_float4(0.f, 0.f, 0.f, 0.f);
        if (row0 + lr < M) {
            xv = *(const float4*)&X[(long)(row0 + lr) * K + kk + lc];
            float4 bb = *(const float4*)&biasIn[kk + lc];
            xv = make_float4(xv.x + bb.x, xv.y + bb.y, xv.z + bb.z, xv.w + bb.w);
        }
        *(float4*)&Xs[lr][lc] = xv;
        *(float4*)&Ws[wr][wc] = *(const float4*)&W[(long)(kk + wr) * 64 + wc];
        __syncthreads();
        #pragma unroll
        for (int k = 0; k < 16; k++) {
            float4 wv = *(const float4*)&Ws[k][tx << 2];
            float xr[4];
            #pragma unroll
            for (int i = 0; i < 4; i++) xr[i] = Xs[ty + (i << 4)][k];
            #pragma unroll
            for (int i = 0; i < 4; i++) {
                acc[i][0] = fmaf(xr[i], wv.x, acc[i][0]);
                acc[i][1] = fmaf(xr[i], wv.y, acc[i][1]);
                acc[i][2] = fmaf(xr[i], wv.z, acc[i][2]);
                acc[i][3] = fmaf(xr[i], wv.w, acc[i][3]);
            }
        }
        __syncthreads();
    }

    #pragma unroll
    for (int i = 0; i < 4; i++) {
        int r = row0 + ty + (i << 4);
        if (r < M) {
            float d = dinvOut ? dinvOut[r] : 1.0f;
            __half2 h0 = __floats2half2_rn(acc[i][0] * d, acc[i][1] * d);
            __half2 h1 = __floats2half2_rn(acc[i][2] * d, acc[i][3] * d);
            uint2 u;
            u.x = *(uint32_t*)&h0;
            u.y = *(uint32_t*)&h1;
            *(uint2*)&outH[(long)r * 64 + (tx << 2)] = u;
        }
    }
}

// ---------------- link predictor (fp16 tables) -------------------------------
__global__ void k_link(const int* __restrict__ ep, const int* __restrict__ es,
                       const __half* __restrict__ A, const __half* __restrict__ B,
                       const float* __restrict__ cvec, const float* __restrict__ wl2,
                       const float* __restrict__ bl2, float* __restrict__ out) {
    int lane = threadIdx.x & 31;
    int half = lane >> 4;
    int sub = lane & 15;
    int warp = (blockIdx.x * blockDim.x + threadIdx.x) >> 5;
    if (warp * 2 >= ELNK) return;
    int e = warp * 2 + half;

    float4 c4 = *(const float4*)&cvec[sub << 2];
    float4 w4 = *(const float4*)&wl2[sub << 2];

    long pi = (long)ep[e];
    long si = (long)es[e];
    uint2 au = *(const uint2*)&A[pi * 64 + (sub << 2)];
    uint2 bu = *(const uint2*)&B[si * 64 + (sub << 2)];
    float2 a0 = __half22float2(*(__half2*)&au.x);
    float2 a1 = __half22float2(*(__half2*)&au.y);
    float2 b0 = __half22float2(*(__half2*)&bu.x);
    float2 b1 = __half22float2(*(__half2*)&bu.y);

    float r = fmaxf(a0.x + b0.x + c4.x, 0.f) * w4.x
            + fmaxf(a0.y + b0.y + c4.y, 0.f) * w4.y
            + fmaxf(a1.x + b1.x + c4.z, 0.f) * w4.z
            + fmaxf(a1.y + b1.y + c4.w, 0.f) * w4.w;

    #pragma unroll
    for (int off = 8; off > 0; off >>= 1)
        r += __shfl_down_sync(0xffffffffu, r, off, 16);

    if (sub == 0) out[e] = r + bl2[0];
}

// ---------------- launch ----------------------------------------------------
extern "C" void kernel_launch(void* const* d_in, const int* in_sizes, int n_in,
                              void* d_out, int out_size) {
    const float* x_p  = (const float*)d_in[0];
    const float* x_s  = (const float*)d_in[1];
    const int*   ei_p = (const int*)d_in[2];
    const int*   ei_s = (const int*)d_in[3];
    const int*   ep   = (const int*)d_in[4];
    const int*   es   = (const int*)d_in[5];
    const float *Wp1 = (const float*)d_in[6],  *bp1 = (const float*)d_in[7];
    const float *Ws1 = (const float*)d_in[8],  *bs1 = (const float*)d_in[9];
    const float *Wp2 = (const float*)d_in[10], *bp2 = (const float*)d_in[11];
    const float *Ws2 = (const float*)d_in[12], *bs2 = (const float*)d_in[13];
    const float *Wproj = (const float*)d_in[14], *bproj = (const float*)d_in[15];
    const float *Wl1 = (const float*)d_in[16], *bl1 = (const float*)d_in[17];
    const float *Wl2 = (const float*)d_in[18], *bl2 = (const float*)d_in[19];
    float* out = (float*)d_out;

    float* scratch = nullptr;
    cudaGetSymbolAddress((void**)&scratch, g_scratch);
    float* P0 = scratch + OFF_P0;
    __half* P1h = (__half*)(scratch + OFF_P1);
    float* P2 = scratch + OFF_P2;
    float* S0 = scratch + OFF_S0;
    __half* S1h = (__half*)(scratch + OFF_S1);
    float* S2 = scratch + OFF_S2;
    __half* P2h = (__half*)(scratch + OFF_P2);
    __half* S2h = (__half*)(scratch + OFF_S2);
    float* dinvP = scratch + OFF_DP;
    float* dinvS = scratch + OFF_DS;
    float* Mp = scratch + OFF_MP;
    float* Ms = scratch + OFF_MS;
    float* cv = scratch + OFF_C;
    int* cnt  = (int*)(scratch + OFF_CNT);
    int* cntP = cnt;
    int* cntS = cnt + NPROT;
    int* offP = (int*)(scratch + OFF_OFFP);
    int* offS = (int*)(scratch + OFF_OFFS);
    int* curP = (int*)(scratch + OFF_CURP);
    int* curS = (int*)(scratch + OFF_CURS);
    int* csrP = (int*)(scratch + OFF_CSRP);
    int* csrS = (int*)(scratch + OFF_CSRS);

    const int TC_SMEM = 2 * TCBUF;   // 32 KB (B hi/lo, double buffered)
    cudaFuncSetAttribute(k_gemm_tc<PDIM>, cudaFuncAttributeMaxDynamicSharedMemorySize, TC_SMEM);
    cudaFuncSetAttribute(k_gemm_tc<SDIM>, cudaFuncAttributeMaxDynamicSharedMemorySize, TC_SMEM);

    const int T = 256;
    const int gP = (NPROT + 63) / 64;
    const int gS = (NSUB + 63) / 64;
    const int gPt = (NPROT + 127) / 128;
    const int gSt = (NSUB + 127) / 128;
    const int aggP = (int)(((long)NPROT * 8 + T - 1) / T);
    const int aggS = (int)(((long)NSUB * 8 + T - 1) / T);

    k_zero_cnt<<<(NPROT + NSUB + T - 1) / T, T>>>(cnt, NPROT + NSUB);                // 0
    k_count_int<<<(EPROT + ESUB + T - 1) / T, T>>>(ei_p + EPROT, ei_s + ESUB,
                                                   cntP, cntS);                      // 1
    k_rsqrt_prep<<<(NPROT + NSUB + T - 1) / T, T>>>(cnt, dinvP, Wproj, bproj,
                                                    Wl1, bl1, Mp, Ms, cv);           // 2
    // ---- protein conv1 GEMM (profiled, idx 3) ----
    k_gemm_tc<PDIM><<<gPt, T, TC_SMEM>>>(x_p, Wp1, dinvP, P1h, NPROT);               // 3
    // ---- CSR build ----
    k_scan<<<2, 1024>>>(cntP, cntS, offP, offS, curP, curS);                         // 4
    k_fill_csr<<<(EPROT + ESUB + T - 1) / T, T>>>(ei_p, ei_p + EPROT,
                                                  ei_s, ei_s + ESUB,
                                                  curP, curS, csrP, csrS);           // 5
    // ---- protein chain ----
    k_aggregate<<<aggP, T>>>(offP, csrP, dinvP, P1h, P2, NPROT);                     // 6
    k_gemm_n64<HDIM><<<gP, T>>>(P2, Wp2, dinvP, bp1, P1h, NPROT);                    // 7
    k_aggregate<<<aggP, T>>>(offP, csrP, dinvP, P1h, P0, NPROT);                     // 8
    k_gemm_n64<HDIM><<<gP, T>>>(P0, Mp, nullptr, bp2, P2h, NPROT);                   // 9
    // ---- substrate chain ----
    k_gemm_tc<SDIM><<<gSt, T, TC_SMEM>>>(x_s, Ws1, dinvS, S1h, NSUB);                // 10
    k_aggregate<<<aggS, T>>>(offS, csrS, dinvS, S1h, S2, NSUB);                      // 11
    k_gemm_n64<HDIM><<<gS, T>>>(S2, Ws2, dinvS, bs1, S1h, NSUB);                     // 12
    k_aggregate<<<aggS, T>>>(offS, csrS, dinvS, S1h, S0, NSUB);                      // 13
    k_gemm_n64<HDIM><<<gS, T>>>(S0, Ms, nullptr, bs2, S2h, NSUB);                    // 14
    // ---- link prediction ----
    int linkBlocks = (int)(((long)(ELNK / 2) * 32 + T - 1) / T);
    k_link<<<linkBlocks, T>>>(ep, es, P2h, S2h, cv, Wl2, bl2, out);                  // 15
}